// round 5
// baseline (speedup 1.0000x reference)
#include <cuda_runtime.h>
#include <math.h>
#include <stdint.h>

#define BB   2
#define TT   1024
#define EE   1024
#define HH   16
#define HD   64
#define LL   8
#define FF_  4096
#define VV   32000
#define MROWS (BB*TT)          // 2048

// ---------------- scratch ----------------
__device__ float g_x  [MROWS*EE];
__device__ float g_h  [MROWS*EE];
__device__ float g_q  [MROWS*EE];
__device__ float g_k  [MROWS*EE];
__device__ float g_v  [MROWS*EE];
__device__ float g_o  [MROWS*EE];
__device__ float g_ff [MROWS*FF_];
__device__ float g_rowloss[MROWS];

// ---------------- helpers ----------------
__device__ __forceinline__ uint32_t cvt_tf32(float x) {
    uint32_t u;
    asm("cvt.rna.tf32.f32 %0, %1;" : "=r"(u) : "f"(x));
    return u;
}
__device__ __forceinline__ float f2tf32f(float x) { return __uint_as_float(cvt_tf32(x)); }

__device__ __forceinline__ void mma_tf32(float* d, const uint32_t* a, const uint32_t* b) {
    asm volatile(
        "mma.sync.aligned.m16n8k8.row.col.f32.tf32.tf32.f32 "
        "{%0,%1,%2,%3}, {%4,%5,%6,%7}, {%8,%9}, {%0,%1,%2,%3};"
        : "+f"(d[0]), "+f"(d[1]), "+f"(d[2]), "+f"(d[3])
        : "r"(a[0]), "r"(a[1]), "r"(a[2]), "r"(a[3]), "r"(b[0]), "r"(b[1]));
}

__device__ __forceinline__ void cp16(float* s, const float* g) {
    uint32_t sa = (uint32_t)__cvta_generic_to_shared(s);
    asm volatile("cp.async.ca.shared.global [%0], [%1], 16;" :: "r"(sa), "l"(g));
}
#define CP_COMMIT() asm volatile("cp.async.commit_group;")

// fast exp on FMA/ALU pipes
__device__ __forceinline__ float fexp(float x) {
    float y = fmaxf(x * 1.44269504f, -126.0f);
    float t = y + 12582912.0f;
    int   e = __float_as_int(t);
    float r = t - 12582912.0f;
    float f = y - r;
    float p = 1.0f + f * (0.693147180f + f * (0.240226507f + f * (0.055504109f +
                     f * (0.009618130f + f * 0.001333356f))));
    return __int_as_float((e - 0x4B400000 + 127) << 23) * p;
}

// ---------------- embedding ----------------
__global__ void embed_kernel(const int* __restrict__ ctx, const float* __restrict__ tok,
                             const float* __restrict__ pos, float* __restrict__ x)
{
    int row = blockIdx.x;
    int t   = row % TT;
    int token = ctx[row];
    int tid = threadIdx.x;
    float4 te = ((const float4*)(tok + (size_t)token * EE))[tid];
    float4 pe = ((const float4*)(pos + (size_t)t * EE))[tid];
    ((float4*)(x + (size_t)row * EE))[tid] =
        make_float4(te.x + pe.x, te.y + pe.y, te.z + pe.z, te.w + pe.w);
}

// ---------------- layernorm: single-pass, rounds output to tf32 ----------------
__global__ void ln_kernel(const float* __restrict__ x, const float* __restrict__ g,
                          const float* __restrict__ b, float* __restrict__ y)
{
    int row = blockIdx.x, tid = threadIdx.x;
    float4 xv = ((const float4*)(x + (size_t)row * EE))[tid];
    float s = xv.x + xv.y + xv.z + xv.w;
    float q = xv.x * xv.x + xv.y * xv.y + xv.z * xv.z + xv.w * xv.w;
    #pragma unroll
    for (int o = 16; o; o >>= 1) {
        s += __shfl_xor_sync(0xffffffffu, s, o);
        q += __shfl_xor_sync(0xffffffffu, q, o);
    }
    __shared__ float ss[8], sq[8];
    int w = tid >> 5;
    if ((tid & 31) == 0) { ss[w] = s; sq[w] = q; }
    __syncthreads();
    if (tid < 32) {
        s = (tid < 8) ? ss[tid] : 0.f;
        q = (tid < 8) ? sq[tid] : 0.f;
        #pragma unroll
        for (int o = 4; o; o >>= 1) {
            s += __shfl_xor_sync(0xffffffffu, s, o);
            q += __shfl_xor_sync(0xffffffffu, q, o);
        }
        if (tid == 0) { ss[0] = s; sq[0] = q; }
    }
    __syncthreads();
    float mu  = ss[0] * (1.0f / EE);
    float var = fmaxf(sq[0] * (1.0f / EE) - mu * mu, 0.f);
    float rs  = rsqrtf(var + 1e-5f);
    float4 gv = ((const float4*)g)[tid], bv = ((const float4*)b)[tid];
    float4 yv;
    yv.x = f2tf32f((xv.x - mu) * rs * gv.x + bv.x);
    yv.y = f2tf32f((xv.y - mu) * rs * gv.y + bv.y);
    yv.z = f2tf32f((xv.z - mu) * rs * gv.z + bv.z);
    yv.w = f2tf32f((xv.w - mu) * rs * gv.w + bv.w);
    ((float4*)(y + (size_t)row * EE))[tid] = yv;
}

// ---------------- tf32 GEMM: 128x128 CTA tile, 4 warps, 64x64 warp tiles ----------------
// A[M,K] pre-rounded tf32; W[K,N] raw fp32 (cvt at fragment load).
// 3-stage cp.async pipeline. Up to 3 weight/output chunks of width wN.
#define ASTR 36
#define BSTR 136
#define ASZ (128*ASTR)
#define BSZ (32*BSTR)

__global__ __launch_bounds__(128) void tgemm_kernel(
    const float* __restrict__ A,
    const float* __restrict__ w0, const float* __restrict__ w1, const float* __restrict__ w2,
    int wN,
    const float* __restrict__ bias, const float* __restrict__ res,
    float* c0, float* c1, float* c2,
    int K, int relu, int rnd)
{
    extern __shared__ float sm[];
    float* As = sm;
    float* Bs = sm + 3 * ASZ;

    int tid = threadIdx.x;
    int warp = tid >> 5, lane = tid & 31;
    int g = lane >> 2, t = lane & 3;
    int wm = (warp & 1) * 64;
    int wn = (warp >> 1) * 64;
    int row0 = blockIdx.y * 128;
    int col0 = blockIdx.x * 128;

    int chunk = col0 / wN;
    int lcol0 = col0 - chunk * wN;
    const float* W = (chunk == 0) ? w0 : (chunk == 1 ? w1 : w2);
    float* C = (chunk == 0) ? c0 : (chunk == 1 ? c1 : c2);
    const float* Ab = A + (size_t)row0 * K;
    const float* Wb = W + lcol0;

    float acc[4][8][4] = {};

    auto issue = [&](int st, int k0) {
        float* as = As + st * ASZ;
        float* bs = Bs + st * BSZ;
        #pragma unroll
        for (int i = 0; i < 8; i++) {
            int idx = tid + i * 128;
            int m = idx >> 3, kq = (idx & 7) * 4;
            cp16(&as[m * ASTR + kq], Ab + (size_t)m * K + k0 + kq);
        }
        #pragma unroll
        for (int i = 0; i < 8; i++) {
            int idx = tid + i * 128;
            int kr = idx >> 5, nq = (idx & 31) * 4;
            cp16(&bs[kr * BSTR + nq], Wb + (size_t)(k0 + kr) * wN + nq);
        }
    };
    auto compute = [&](int st) {
        const float* as = As + st * ASZ;
        const float* bs = Bs + st * BSZ;
        #pragma unroll
        for (int kk = 0; kk < 4; kk++) {
            int kb = kk * 8;
            uint32_t af[4][4], bf[8][2];
            #pragma unroll
            for (int mi = 0; mi < 4; mi++) {
                int r = wm + mi * 16 + g;
                af[mi][0] = __float_as_uint(as[r * ASTR + kb + t]);
                af[mi][1] = __float_as_uint(as[(r + 8) * ASTR + kb + t]);
                af[mi][2] = __float_as_uint(as[r * ASTR + kb + t + 4]);
                af[mi][3] = __float_as_uint(as[(r + 8) * ASTR + kb + t + 4]);
            }
            #pragma unroll
            for (int ni = 0; ni < 8; ni++) {
                int c = wn + ni * 8 + g;
                bf[ni][0] = cvt_tf32(bs[(kb + t) * BSTR + c]);
                bf[ni][1] = cvt_tf32(bs[(kb + t + 4) * BSTR + c]);
            }
            #pragma unroll
            for (int mi = 0; mi < 4; mi++)
                #pragma unroll
                for (int ni = 0; ni < 8; ni++)
                    mma_tf32(acc[mi][ni], af[mi], bf[ni]);
        }
    };

    issue(0, 0);  CP_COMMIT();
    issue(1, 32); CP_COMMIT();
    int s = 0;
    for (int k0 = 0; k0 < K; k0 += 32) {
        asm volatile("cp.async.wait_group 1;");
        __syncthreads();
        int kpf = k0 + 64;
        if (kpf < K) issue((s + 2) % 3, kpf);
        CP_COMMIT();
        compute(s);
        s = (s + 1) % 3;
        __syncthreads();
    }

    #pragma unroll
    for (int mi = 0; mi < 4; mi++) {
        int r = row0 + wm + mi * 16 + g;
        #pragma unroll
        for (int ni = 0; ni < 8; ni++) {
            int c = lcol0 + wn + ni * 8 + t * 2;
            float v0 = acc[mi][ni][0], v1 = acc[mi][ni][1];
            float v2 = acc[mi][ni][2], v3 = acc[mi][ni][3];
            if (bias) { float b0 = bias[c], b1 = bias[c + 1]; v0 += b0; v1 += b1; v2 += b0; v3 += b1; }
            if (res) {
                v0 += res[(size_t)r * wN + c];       v1 += res[(size_t)r * wN + c + 1];
                v2 += res[(size_t)(r + 8) * wN + c]; v3 += res[(size_t)(r + 8) * wN + c + 1];
            }
            if (relu) { v0 = fmaxf(v0, 0.f); v1 = fmaxf(v1, 0.f); v2 = fmaxf(v2, 0.f); v3 = fmaxf(v3, 0.f); }
            if (rnd)  { v0 = f2tf32f(v0); v1 = f2tf32f(v1); v2 = f2tf32f(v2); v3 = f2tf32f(v3); }
            *(float2*)&C[(size_t)r * wN + c]       = make_float2(v0, v1);
            *(float2*)&C[(size_t)(r + 8) * wN + c] = make_float2(v2, v3);
        }
    }
}

// ---------------- fused flash attention (causal, HD=64, scale=1/32) ----------------
// q,k,v pre-rounded tf32; output rounded to tf32.
#define PQ 68
#define PV 72
__global__ __launch_bounds__(128, 3) void flash_kernel(
    const float* __restrict__ q, const float* __restrict__ k,
    const float* __restrict__ v, float* __restrict__ o)
{
    extern __shared__ float sm[];
    float* Qs = sm;
    float* Ks = Qs + 64 * PQ;
    float* Ps = Ks + 64 * PQ;
    float* Vs = Ps + 64 * PQ;

    int qt = blockIdx.x, bh = blockIdx.y;
    int b = bh >> 4, h = bh & 15;
    int q0 = qt * 64;

    int tid = threadIdx.x;
    int warp = tid >> 5, lane = tid & 31;
    int g = lane >> 2, t = lane & 3;
    int wq = warp * 16;
    int r0 = wq + g, r1 = wq + g + 8;

    for (int i = tid; i < 1024; i += 128) {
        int r = i >> 4, d = (i & 15) * 4;
        *(float4*)&Qs[r * PQ + d] = *(const float4*)(q + (size_t)(b * TT + q0 + r) * EE + h * 64 + d);
    }

    float accO[8][4] = {};
    float mr0 = -1e30f, mr1 = -1e30f, lr0 = 0.f, lr1 = 0.f;
    const float scale = 0.03125f;

    for (int kt = 0; kt <= qt; kt++) {
        int k0 = kt * 64;
        __syncthreads();
        for (int i = tid; i < 1024; i += 128) {
            int r = i >> 4, d = (i & 15) * 4;
            *(float4*)&Ks[r * PQ + d] = *(const float4*)(k + (size_t)(b * TT + k0 + r) * EE + h * 64 + d);
            *(float4*)&Vs[r * PV + d] = *(const float4*)(v + (size_t)(b * TT + k0 + r) * EE + h * 64 + d);
        }
        __syncthreads();

        float accS[8][4] = {};
        #pragma unroll
        for (int kb = 0; kb < 64; kb += 8) {
            uint32_t af[4];
            af[0] = __float_as_uint(Qs[r0 * PQ + kb + t]);
            af[1] = __float_as_uint(Qs[r1 * PQ + kb + t]);
            af[2] = __float_as_uint(Qs[r0 * PQ + kb + t + 4]);
            af[3] = __float_as_uint(Qs[r1 * PQ + kb + t + 4]);
            #pragma unroll
            for (int ni = 0; ni < 8; ni++) {
                uint32_t bf[2];
                bf[0] = __float_as_uint(Ks[(ni * 8 + g) * PQ + kb + t]);
                bf[1] = __float_as_uint(Ks[(ni * 8 + g) * PQ + kb + t + 4]);
                mma_tf32(accS[ni], af, bf);
            }
        }

        bool diag = (kt == qt);
        #pragma unroll
        for (int ni = 0; ni < 8; ni++) {
            int c = ni * 8 + t * 2;
            accS[ni][0] *= scale; accS[ni][1] *= scale;
            accS[ni][2] *= scale; accS[ni][3] *= scale;
            if (diag) {
                if (c     > r0) accS[ni][0] = -1e30f;
                if (c + 1 > r0) accS[ni][1] = -1e30f;
                if (c     > r1) accS[ni][2] = -1e30f;
                if (c + 1 > r1) accS[ni][3] = -1e30f;
            }
        }

        float m0 = -1e30f, m1 = -1e30f;
        #pragma unroll
        for (int ni = 0; ni < 8; ni++) {
            m0 = fmaxf(m0, fmaxf(accS[ni][0], accS[ni][1]));
            m1 = fmaxf(m1, fmaxf(accS[ni][2], accS[ni][3]));
        }
        m0 = fmaxf(m0, __shfl_xor_sync(0xffffffffu, m0, 1));
        m0 = fmaxf(m0, __shfl_xor_sync(0xffffffffu, m0, 2));
        m1 = fmaxf(m1, __shfl_xor_sync(0xffffffffu, m1, 1));
        m1 = fmaxf(m1, __shfl_xor_sync(0xffffffffu, m1, 2));

        float mn0 = fmaxf(mr0, m0), mn1 = fmaxf(mr1, m1);
        float a0 = fexp(mr0 - mn0), a1 = fexp(mr1 - mn1);

        float s0 = 0.f, s1 = 0.f;
        #pragma unroll
        for (int ni = 0; ni < 8; ni++) {
            accS[ni][0] = fexp(accS[ni][0] - mn0);
            accS[ni][1] = fexp(accS[ni][1] - mn0);
            accS[ni][2] = fexp(accS[ni][2] - mn1);
            accS[ni][3] = fexp(accS[ni][3] - mn1);
            s0 += accS[ni][0] + accS[ni][1];
            s1 += accS[ni][2] + accS[ni][3];
        }
        s0 += __shfl_xor_sync(0xffffffffu, s0, 1);
        s0 += __shfl_xor_sync(0xffffffffu, s0, 2);
        s1 += __shfl_xor_sync(0xffffffffu, s1, 1);
        s1 += __shfl_xor_sync(0xffffffffu, s1, 2);

        lr0 = lr0 * a0 + s0;
        lr1 = lr1 * a1 + s1;
        mr0 = mn0; mr1 = mn1;

        #pragma unroll
        for (int ni = 0; ni < 8; ni++) {
            accO[ni][0] *= a0; accO[ni][1] *= a0;
            accO[ni][2] *= a1; accO[ni][3] *= a1;
        }

        #pragma unroll
        for (int ni = 0; ni < 8; ni++) {
            int c = ni * 8 + t * 2;
            Ps[r0 * PQ + c]     = f2tf32f(accS[ni][0]);
            Ps[r0 * PQ + c + 1] = f2tf32f(accS[ni][1]);
            Ps[r1 * PQ + c]     = f2tf32f(accS[ni][2]);
            Ps[r1 * PQ + c + 1] = f2tf32f(accS[ni][3]);
        }
        __syncwarp();

        #pragma unroll
        for (int kb = 0; kb < 64; kb += 8) {
            uint32_t af[4];
            af[0] = __float_as_uint(Ps[r0 * PQ + kb + t]);
            af[1] = __float_as_uint(Ps[r1 * PQ + kb + t]);
            af[2] = __float_as_uint(Ps[r0 * PQ + kb + t + 4]);
            af[3] = __float_as_uint(Ps[r1 * PQ + kb + t + 4]);
            #pragma unroll
            for (int ni = 0; ni < 8; ni++) {
                uint32_t bf[2];
                bf[0] = __float_as_uint(Vs[(kb + t) * PV + ni * 8 + g]);
                bf[1] = __float_as_uint(Vs[(kb + t + 4) * PV + ni * 8 + g]);
                mma_tf32(accO[ni], af, bf);
            }
        }
    }

    float i0 = 1.f / lr0, i1 = 1.f / lr1;
    #pragma unroll
    for (int ni = 0; ni < 8; ni++) {
        int d = ni * 8 + t * 2;
        *(float2*)(o + (size_t)(b * TT + q0 + r0) * EE + h * 64 + d) =
            make_float2(f2tf32f(accO[ni][0] * i0), f2tf32f(accO[ni][1] * i0));
        *(float2*)(o + (size_t)(b * TT + q0 + r1) * EE + h * 64 + d) =
            make_float2(f2tf32f(accO[ni][2] * i1), f2tf32f(accO[ni][3] * i1));
    }
}

// ---------------- cross-entropy ----------------
__global__ void loss_row_kernel(const float* __restrict__ logits, const int* __restrict__ targets,
                                float* __restrict__ rowloss)
{
    int row = blockIdx.x;
    const float* lr = logits + (size_t)row * VV;
    __shared__ float red[256];
    int tid = threadIdx.x;

    float m = -1e30f;
    for (int i = tid; i < VV / 4; i += 256) {
        float4 v = ((const float4*)lr)[i];
        m = fmaxf(m, fmaxf(fmaxf(v.x, v.y), fmaxf(v.z, v.w)));
    }
    red[tid] = m; __syncthreads();
    for (int o = 128; o > 0; o >>= 1) { if (tid < o) red[tid] = fmaxf(red[tid], red[tid + o]); __syncthreads(); }
    m = red[0]; __syncthreads();

    float s = 0.f;
    for (int i = tid; i < VV / 4; i += 256) {
        float4 v = ((const float4*)lr)[i];
        s += fexp(v.x - m) + fexp(v.y - m) + fexp(v.z - m) + fexp(v.w - m);
    }
    red[tid] = s; __syncthreads();
    for (int o = 128; o > 0; o >>= 1) { if (tid < o) red[tid] += red[tid + o]; __syncthreads(); }

    if (tid == 0) {
        float lse = m + logf(red[0]);
        rowloss[row] = lse - lr[targets[row]];
    }
}

__global__ void loss_reduce_kernel(const float* __restrict__ rowloss, float* __restrict__ out)
{
    __shared__ float red[256];
    int tid = threadIdx.x;
    float s = 0.f;
    for (int i = tid; i < MROWS; i += 256) s += rowloss[i];
    red[tid] = s; __syncthreads();
    for (int o = 128; o > 0; o >>= 1) { if (tid < o) red[tid] += red[tid + o]; __syncthreads(); }
    if (tid == 0) out[0] = red[0] * (1.0f / MROWS);
}

// ---------------- host orchestration ----------------
#define SMEMG (3 * (ASZ + BSZ) * 4)         // 107520
#define SMEMF ((3*64*PQ + 64*PV) * 4)       // 70656

extern "C" void kernel_launch(void* const* d_in, const int* in_sizes, int n_in,
                              void* d_out, int out_size)
{
    const int*   ctx  = (const int*)  d_in[0];
    const int*   tgt  = (const int*)  d_in[1];
    const float* tok  = (const float*)d_in[2];
    const float* pos  = (const float*)d_in[3];
    const float* Wq   = (const float*)d_in[4];
    const float* Wk   = (const float*)d_in[5];
    const float* Wv   = (const float*)d_in[6];
    const float* Wo   = (const float*)d_in[7];
    const float* bo   = (const float*)d_in[8];
    const float* ln1g = (const float*)d_in[9];
    const float* ln1b = (const float*)d_in[10];
    const float* ln2g = (const float*)d_in[11];
    const float* ln2b = (const float*)d_in[12];
    const float* W1   = (const float*)d_in[13];
    const float* b1   = (const float*)d_in[14];
    const float* W2   = (const float*)d_in[15];
    const float* b2   = (const float*)d_in[16];
    const float* lnfg = (const float*)d_in[17];
    const float* lnfb = (const float*)d_in[18];
    const float* Wlm  = (const float*)d_in[19];
    const float* blm  = (const float*)d_in[20];

    static float *px = nullptr, *ph, *pq, *pk, *pv, *po, *pff, *prl;
    if (!px) {
        cudaGetSymbolAddress((void**)&px,  g_x);
        cudaGetSymbolAddress((void**)&ph,  g_h);
        cudaGetSymbolAddress((void**)&pq,  g_q);
        cudaGetSymbolAddress((void**)&pk,  g_k);
        cudaGetSymbolAddress((void**)&pv,  g_v);
        cudaGetSymbolAddress((void**)&po,  g_o);
        cudaGetSymbolAddress((void**)&pff, g_ff);
        cudaGetSymbolAddress((void**)&prl, g_rowloss);
        cudaFuncSetAttribute(tgemm_kernel, cudaFuncAttributeMaxDynamicSharedMemorySize, SMEMG);
        cudaFuncSetAttribute(flash_kernel, cudaFuncAttributeMaxDynamicSharedMemorySize, SMEMF);
    }
    float* out = (float*)d_out;

    embed_kernel<<<MROWS, 256>>>(ctx, tok, pos, px);

    dim3 gQKV(24, 16);     // N=3072 (3 chunks of 1024)
    dim3 gEo (8, 16);      // N=1024
    dim3 gF1 (32, 16);     // N=4096
    dim3 gLM (250, 16);    // N=32000
    dim3 gFA (16, 32);

    for (int l = 0; l < LL; l++) {
        size_t oE = (size_t)l * EE * EE, oF1 = (size_t)l * EE * FF_, oF2 = (size_t)l * FF_ * EE;

        ln_kernel<<<MROWS, 256>>>(px, ln1g + l * EE, ln1b + l * EE, ph);

        tgemm_kernel<<<gQKV, 128, SMEMG>>>(ph, Wq + oE, Wk + oE, Wv + oE, EE,
                                           nullptr, nullptr, pq, pk, pv, EE, 0, 1);

        flash_kernel<<<gFA, 128, SMEMF>>>(pq, pk, pv, po);

        tgemm_kernel<<<gEo, 128, SMEMG>>>(po, Wo + oE, Wo + oE, Wo + oE, EE,
                                          bo + l * EE, px, px, px, px, EE, 0, 0);

        ln_kernel<<<MROWS, 256>>>(px, ln2g + l * EE, ln2b + l * EE, ph);

        tgemm_kernel<<<gF1, 128, SMEMG>>>(ph, W1 + oF1, W1 + oF1, W1 + oF1, FF_,
                                          b1 + l * FF_, nullptr, pff, pff, pff, EE, 1, 1);

        tgemm_kernel<<<gEo, 128, SMEMG>>>(pff, W2 + oF2, W2 + oF2, W2 + oF2, EE,
                                          b2 + l * EE, px, px, px, px, FF_, 0, 0);
    }

    ln_kernel<<<MROWS, 256>>>(px, lnfg, lnfb, ph);
    tgemm_kernel<<<gLM, 128, SMEMG>>>(ph, Wlm, Wlm, Wlm, VV,
                                      blm, nullptr, out, out, out, EE, 0, 0);

    if (out_size > MROWS * VV) {
        loss_row_kernel<<<MROWS, 256>>>(out, tgt, prl);
        loss_reduce_kernel<<<1, 256>>>(prl, out + (size_t)MROWS * VV);
    }
}

// round 6
// speedup vs baseline: 1.5902x; 1.5902x over previous
#include <cuda_runtime.h>
#include <cuda_fp16.h>
#include <math.h>
#include <stdint.h>

#define BB   2
#define TT   1024
#define EE   1024
#define HH   16
#define HD   64
#define LL   8
#define FF_  4096
#define VV   32000
#define MROWS (BB*TT)          // 2048

// ---------------- scratch ----------------
__device__ float  g_x  [MROWS*EE];            // fp32 residual
__device__ __half g_h  [MROWS*EE];            // LN outputs (GEMM A)
__device__ __half g_q  [MROWS*EE];
__device__ __half g_k  [MROWS*EE];
__device__ __half g_v  [MROWS*EE];
__device__ __half g_o  [MROWS*EE];
__device__ __half g_ff [MROWS*FF_];
__device__ float  g_rowloss[MROWS];
// transposed fp16 weights, [N][K] K-major
__device__ __half g_whq[LL*EE*EE];
__device__ __half g_whk[LL*EE*EE];
__device__ __half g_whv[LL*EE*EE];
__device__ __half g_who[LL*EE*EE];
__device__ __half g_wh1[LL*EE*FF_];
__device__ __half g_wh2[LL*FF_*EE];
__device__ __half g_whlm[(size_t)EE*VV];

// ---------------- helpers ----------------
__device__ __forceinline__ void mma_f16(float* d, const uint32_t* a, const uint32_t* b) {
    asm volatile(
        "mma.sync.aligned.m16n8k16.row.col.f32.f16.f16.f32 "
        "{%0,%1,%2,%3}, {%4,%5,%6,%7}, {%8,%9}, {%0,%1,%2,%3};"
        : "+f"(d[0]), "+f"(d[1]), "+f"(d[2]), "+f"(d[3])
        : "r"(a[0]), "r"(a[1]), "r"(a[2]), "r"(a[3]), "r"(b[0]), "r"(b[1]));
}

__device__ __forceinline__ void cp16h(__half* s, const __half* g) {
    uint32_t sa = (uint32_t)__cvta_generic_to_shared(s);
    asm volatile("cp.async.ca.shared.global [%0], [%1], 16;" :: "r"(sa), "l"(g));
}
#define CP_COMMIT() asm volatile("cp.async.commit_group;")

// fast exp on FMA/ALU pipes
__device__ __forceinline__ float fexp(float x) {
    float y = fmaxf(x * 1.44269504f, -126.0f);
    float t = y + 12582912.0f;
    int   e = __float_as_int(t);
    float r = t - 12582912.0f;
    float f = y - r;
    float p = 1.0f + f * (0.693147180f + f * (0.240226507f + f * (0.055504109f +
                     f * (0.009618130f + f * 0.001333356f))));
    return __int_as_float((e - 0x4B400000 + 127) << 23) * p;
}

// ---------------- weight transpose + fp16 convert: in[R][C] fp32 -> out[C][R] fp16 ----
__global__ void transp_h(const float* __restrict__ in, __half* __restrict__ out, int R, int C)
{
    __shared__ float t[32][33];
    size_t lo = (size_t)blockIdx.z * R * C;
    in += lo; out += lo;
    int c0 = blockIdx.x * 32, r0 = blockIdx.y * 32;
    for (int i = threadIdx.y; i < 32; i += 8)
        t[i][threadIdx.x] = in[(size_t)(r0 + i) * C + c0 + threadIdx.x];
    __syncthreads();
    for (int i = threadIdx.y; i < 32; i += 8)
        out[(size_t)(c0 + i) * R + r0 + threadIdx.x] = __float2half_rn(t[threadIdx.x][i]);
}

// ---------------- embedding ----------------
__global__ void embed_kernel(const int* __restrict__ ctx, const float* __restrict__ tok,
                             const float* __restrict__ pos, float* __restrict__ x)
{
    int row = blockIdx.x;
    int t   = row % TT;
    int token = ctx[row];
    int tid = threadIdx.x;
    float4 te = ((const float4*)(tok + (size_t)token * EE))[tid];
    float4 pe = ((const float4*)(pos + (size_t)t * EE))[tid];
    ((float4*)(x + (size_t)row * EE))[tid] =
        make_float4(te.x + pe.x, te.y + pe.y, te.z + pe.z, te.w + pe.w);
}

// ---------------- layernorm: fp32 in, fp16 out ----------------
__global__ void ln_kernel(const float* __restrict__ x, const float* __restrict__ g,
                          const float* __restrict__ b, __half* __restrict__ y)
{
    int row = blockIdx.x, tid = threadIdx.x;
    float4 xv = ((const float4*)(x + (size_t)row * EE))[tid];
    float s = xv.x + xv.y + xv.z + xv.w;
    float q = xv.x * xv.x + xv.y * xv.y + xv.z * xv.z + xv.w * xv.w;
    #pragma unroll
    for (int o = 16; o; o >>= 1) {
        s += __shfl_xor_sync(0xffffffffu, s, o);
        q += __shfl_xor_sync(0xffffffffu, q, o);
    }
    __shared__ float ss[8], sq[8];
    int w = tid >> 5;
    if ((tid & 31) == 0) { ss[w] = s; sq[w] = q; }
    __syncthreads();
    if (tid < 32) {
        s = (tid < 8) ? ss[tid] : 0.f;
        q = (tid < 8) ? sq[tid] : 0.f;
        #pragma unroll
        for (int o = 4; o; o >>= 1) {
            s += __shfl_xor_sync(0xffffffffu, s, o);
            q += __shfl_xor_sync(0xffffffffu, q, o);
        }
        if (tid == 0) { ss[0] = s; sq[0] = q; }
    }
    __syncthreads();
    float mu  = ss[0] * (1.0f / EE);
    float var = fmaxf(sq[0] * (1.0f / EE) - mu * mu, 0.f);
    float rs  = rsqrtf(var + 1e-5f);
    float4 gv = ((const float4*)g)[tid], bv = ((const float4*)b)[tid];
    __half2 h0 = __floats2half2_rn((xv.x - mu) * rs * gv.x + bv.x,
                                   (xv.y - mu) * rs * gv.y + bv.y);
    __half2 h1 = __floats2half2_rn((xv.z - mu) * rs * gv.z + bv.z,
                                   (xv.w - mu) * rs * gv.w + bv.w);
    uint2 pack = make_uint2(*(uint32_t*)&h0, *(uint32_t*)&h1);
    *(uint2*)(y + (size_t)row * EE + tid * 4) = pack;
}

// ---------------- fp16 GEMM: 128x128 CTA tile, 8 warps, 32x64 warp tiles ----------------
// A[M,K] fp16; W[N,K] fp16 (pre-transposed). 3-stage cp.async. Up to 3 chunks of width wN.
#define HSTR 40
#define HTSZ (128*HSTR)

__global__ __launch_bounds__(256, 2) void hgemm_kernel(
    const __half* __restrict__ A,
    const __half* __restrict__ w0, const __half* __restrict__ w1, const __half* __restrict__ w2,
    int wN,
    const float* __restrict__ bias, const float* __restrict__ res,
    void* c0, void* c1, void* c2,
    int K, int relu, int outHalf)
{
    extern __shared__ __half sm[];
    __half* As = sm;                  // 3 stages, each [128][40]
    __half* Bs = sm + 3 * HTSZ;       // 3 stages, each [128][40] ([n][k])

    int tid = threadIdx.x;
    int warp = tid >> 5, lane = tid & 31;
    int g = lane >> 2, t = lane & 3;
    int wm = (warp & 3) * 32;
    int wn = (warp >> 2) * 64;
    int row0 = blockIdx.y * 128;
    int col0 = blockIdx.x * 128;

    int chunk = col0 / wN;
    int lcol0 = col0 - chunk * wN;
    const __half* W = (chunk == 0) ? w0 : (chunk == 1 ? w1 : w2);
    void* C = (chunk == 0) ? c0 : (chunk == 1 ? c1 : c2);
    const __half* Ab = A + (size_t)row0 * K;
    const __half* Wb = W + (size_t)lcol0 * K;

    float acc[2][8][4] = {};

    auto issue = [&](int st, int k0) {
        __half* as = As + st * HTSZ;
        __half* bs = Bs + st * HTSZ;
        #pragma unroll
        for (int i = 0; i < 2; i++) {
            int idx = tid + i * 256;
            int m = idx >> 2, kq = (idx & 3) * 8;
            cp16h(&as[m * HSTR + kq], Ab + (size_t)m * K + k0 + kq);
            cp16h(&bs[m * HSTR + kq], Wb + (size_t)m * K + k0 + kq);
        }
    };
    auto compute = [&](int st) {
        const __half* as = As + st * HTSZ;
        const __half* bs = Bs + st * HTSZ;
        #pragma unroll
        for (int kk = 0; kk < 2; kk++) {
            int kb = kk * 16;
            uint32_t af[2][4], bf[8][2];
            #pragma unroll
            for (int mi = 0; mi < 2; mi++) {
                int r = wm + mi * 16 + g;
                af[mi][0] = *(const uint32_t*)&as[r * HSTR + kb + 2 * t];
                af[mi][1] = *(const uint32_t*)&as[(r + 8) * HSTR + kb + 2 * t];
                af[mi][2] = *(const uint32_t*)&as[r * HSTR + kb + 2 * t + 8];
                af[mi][3] = *(const uint32_t*)&as[(r + 8) * HSTR + kb + 2 * t + 8];
            }
            #pragma unroll
            for (int ni = 0; ni < 8; ni++) {
                int n = wn + ni * 8 + g;
                bf[ni][0] = *(const uint32_t*)&bs[n * HSTR + kb + 2 * t];
                bf[ni][1] = *(const uint32_t*)&bs[n * HSTR + kb + 2 * t + 8];
            }
            #pragma unroll
            for (int mi = 0; mi < 2; mi++)
                #pragma unroll
                for (int ni = 0; ni < 8; ni++)
                    mma_f16(acc[mi][ni], af[mi], bf[ni]);
        }
    };

    issue(0, 0);  CP_COMMIT();
    issue(1, 32); CP_COMMIT();
    int s = 0;
    for (int k0 = 0; k0 < K; k0 += 32) {
        asm volatile("cp.async.wait_group 1;");
        __syncthreads();
        int kpf = k0 + 64;
        if (kpf < K) issue((s + 2) % 3, kpf);
        CP_COMMIT();
        compute(s);
        s = (s + 1) % 3;
        __syncthreads();
    }

    #pragma unroll
    for (int mi = 0; mi < 2; mi++) {
        int r = row0 + wm + mi * 16 + g;
        #pragma unroll
        for (int ni = 0; ni < 8; ni++) {
            int c = lcol0 + wn + ni * 8 + t * 2;
            float v0 = acc[mi][ni][0], v1 = acc[mi][ni][1];
            float v2 = acc[mi][ni][2], v3 = acc[mi][ni][3];
            if (bias) { float b0 = bias[c], b1 = bias[c + 1]; v0 += b0; v1 += b1; v2 += b0; v3 += b1; }
            if (res) {
                v0 += res[(size_t)r * wN + c];       v1 += res[(size_t)r * wN + c + 1];
                v2 += res[(size_t)(r + 8) * wN + c]; v3 += res[(size_t)(r + 8) * wN + c + 1];
            }
            if (relu) { v0 = fmaxf(v0, 0.f); v1 = fmaxf(v1, 0.f); v2 = fmaxf(v2, 0.f); v3 = fmaxf(v3, 0.f); }
            if (outHalf) {
                __half* Ch = (__half*)C;
                *(__half2*)&Ch[(size_t)r * wN + c]       = __floats2half2_rn(v0, v1);
                *(__half2*)&Ch[(size_t)(r + 8) * wN + c] = __floats2half2_rn(v2, v3);
            } else {
                float* Cf = (float*)C;
                *(float2*)&Cf[(size_t)r * wN + c]       = make_float2(v0, v1);
                *(float2*)&Cf[(size_t)(r + 8) * wN + c] = make_float2(v2, v3);
            }
        }
    }
}

// ---------------- fused flash attention, fp16 mma (causal, HD=64, scale=1/32) -------
#define FSTR 72
__global__ __launch_bounds__(128, 3) void flash_kernel(
    const __half* __restrict__ q, const __half* __restrict__ k,
    const __half* __restrict__ v, __half* __restrict__ o)
{
    __shared__ __half Qs [64 * FSTR];
    __shared__ __half Ks [64 * FSTR];
    __shared__ __half Ps [64 * FSTR];
    __shared__ __half Vst[64 * FSTR];   // transposed: [d][key]

    int qt = blockIdx.x, bh = blockIdx.y;
    int b = bh >> 4, h = bh & 15;
    int q0 = qt * 64;

    int tid = threadIdx.x;
    int warp = tid >> 5, lane = tid & 31;
    int g = lane >> 2, t = lane & 3;
    int wq = warp * 16;
    int r0 = wq + g;

    // load Q tile (64x64 halfs)
    #pragma unroll
    for (int i = 0; i < 4; i++) {
        int idx = tid + i * 128;
        int r = idx >> 3, dq = (idx & 7) * 8;
        *(uint4*)&Qs[r * FSTR + dq] =
            *(const uint4*)(q + (size_t)(b * TT + q0 + r) * EE + h * 64 + dq);
    }

    float accO[8][4] = {};
    float mr0 = -1e30f, mr1 = -1e30f, lr0 = 0.f, lr1 = 0.f;
    const float scale = 0.03125f;

    for (int kt = 0; kt <= qt; kt++) {
        int k0 = kt * 64;
        __syncthreads();
        // K rows
        #pragma unroll
        for (int i = 0; i < 4; i++) {
            int idx = tid + i * 128;
            int r = idx >> 3, dq = (idx & 7) * 8;
            *(uint4*)&Ks[r * FSTR + dq] =
                *(const uint4*)(k + (size_t)(b * TT + k0 + r) * EE + h * 64 + dq);
        }
        // V transposed: thread handles 2 keys x 4 d
        #pragma unroll
        for (int it = 0; it < 4; it++) {
            int idx = tid + it * 128;
            int key = (idx & 31) * 2;
            int d0 = (idx >> 5) * 4;
            const __half* vp = v + (size_t)(b * TT + k0 + key) * EE + h * 64 + d0;
            __half h0[4], h1[4];
            *(uint2*)h0 = *(const uint2*)vp;
            *(uint2*)h1 = *(const uint2*)(vp + EE);
            #pragma unroll
            for (int j = 0; j < 4; j++)
                *(__half2*)&Vst[(d0 + j) * FSTR + key] = __halves2half2(h0[j], h1[j]);
        }
        __syncthreads();

        // S = Q K^T : 4 k16 steps over d
        float accS[8][4] = {};
        #pragma unroll
        for (int kb = 0; kb < 64; kb += 16) {
            uint32_t af[4];
            af[0] = *(const uint32_t*)&Qs[r0 * FSTR + kb + 2 * t];
            af[1] = *(const uint32_t*)&Qs[(r0 + 8) * FSTR + kb + 2 * t];
            af[2] = *(const uint32_t*)&Qs[r0 * FSTR + kb + 2 * t + 8];
            af[3] = *(const uint32_t*)&Qs[(r0 + 8) * FSTR + kb + 2 * t + 8];
            #pragma unroll
            for (int ni = 0; ni < 8; ni++) {
                uint32_t bf[2];
                bf[0] = *(const uint32_t*)&Ks[(ni * 8 + g) * FSTR + kb + 2 * t];
                bf[1] = *(const uint32_t*)&Ks[(ni * 8 + g) * FSTR + kb + 2 * t + 8];
                mma_f16(accS[ni], af, bf);
            }
        }

        bool diag = (kt == qt);
        #pragma unroll
        for (int ni = 0; ni < 8; ni++) {
            int c = ni * 8 + t * 2;
            accS[ni][0] *= scale; accS[ni][1] *= scale;
            accS[ni][2] *= scale; accS[ni][3] *= scale;
            if (diag) {
                if (c     > r0)     accS[ni][0] = -1e30f;
                if (c + 1 > r0)     accS[ni][1] = -1e30f;
                if (c     > r0 + 8) accS[ni][2] = -1e30f;
                if (c + 1 > r0 + 8) accS[ni][3] = -1e30f;
            }
        }

        float m0 = -1e30f, m1 = -1e30f;
        #pragma unroll
        for (int ni = 0; ni < 8; ni++) {
            m0 = fmaxf(m0, fmaxf(accS[ni][0], accS[ni][1]));
            m1 = fmaxf(m1, fmaxf(accS[ni][2], accS[ni][3]));
        }
        m0 = fmaxf(m0, __shfl_xor_sync(0xffffffffu, m0, 1));
        m0 = fmaxf(m0, __shfl_xor_sync(0xffffffffu, m0, 2));
        m1 = fmaxf(m1, __shfl_xor_sync(0xffffffffu, m1, 1));
        m1 = fmaxf(m1, __shfl_xor_sync(0xffffffffu, m1, 2));

        float mn0 = fmaxf(mr0, m0), mn1 = fmaxf(mr1, m1);
        float a0 = fexp(mr0 - mn0), a1 = fexp(mr1 - mn1);

        float s0 = 0.f, s1 = 0.f;
        #pragma unroll
        for (int ni = 0; ni < 8; ni++) {
            accS[ni][0] = fexp(accS[ni][0] - mn0);
            accS[ni][1] = fexp(accS[ni][1] - mn0);
            accS[ni][2] = fexp(accS[ni][2] - mn1);
            accS[ni][3] = fexp(accS[ni][3] - mn1);
            s0 += accS[ni][0] + accS[ni][1];
            s1 += accS[ni][2] + accS[ni][3];
        }
        s0 += __shfl_xor_sync(0xffffffffu, s0, 1);
        s0 += __shfl_xor_sync(0xffffffffu, s0, 2);
        s1 += __shfl_xor_sync(0xffffffffu, s1, 1);
        s1 += __shfl_xor_sync(0xffffffffu, s1, 2);

        lr0 = lr0 * a0 + s0;
        lr1 = lr1 * a1 + s1;
        mr0 = mn0; mr1 = mn1;

        #pragma unroll
        for (int ni = 0; ni < 8; ni++) {
            accO[ni][0] *= a0; accO[ni][1] *= a0;
            accO[ni][2] *= a1; accO[ni][3] *= a1;
        }

        // P -> smem (fp16), own rows only
        #pragma unroll
        for (int ni = 0; ni < 8; ni++) {
            int c = ni * 8 + 2 * t;
            *(__half2*)&Ps[r0 * FSTR + c]       = __floats2half2_rn(accS[ni][0], accS[ni][1]);
            *(__half2*)&Ps[(r0 + 8) * FSTR + c] = __floats2half2_rn(accS[ni][2], accS[ni][3]);
        }
        __syncwarp();

        // O += P V : 4 k16 steps over keys
        #pragma unroll
        for (int kb = 0; kb < 64; kb += 16) {
            uint32_t af[4];
            af[0] = *(const uint32_t*)&Ps[r0 * FSTR + kb + 2 * t];
            af[1] = *(const uint32_t*)&Ps[(r0 + 8) * FSTR + kb + 2 * t];
            af[2] = *(const uint32_t*)&Ps[r0 * FSTR + kb + 2 * t + 8];
            af[3] = *(const uint32_t*)&Ps[(r0 + 8) * FSTR + kb + 2 * t + 8];
            #pragma unroll
            for (int ni = 0; ni < 8; ni++) {
                uint32_t bf[2];
                bf[0] = *(const uint32_t*)&Vst[(ni * 8 + g) * FSTR + kb + 2 * t];
                bf[1] = *(const uint32_t*)&Vst[(ni * 8 + g) * FSTR + kb + 2 * t + 8];
                mma_f16(accO[ni], af, bf);
            }
        }
    }

    float i0 = 1.f / lr0, i1 = 1.f / lr1;
    #pragma unroll
    for (int ni = 0; ni < 8; ni++) {
        int d = ni * 8 + 2 * t;
        *(__half2*)(o + (size_t)(b * TT + q0 + r0) * EE + h * 64 + d) =
            __floats2half2_rn(accO[ni][0] * i0, accO[ni][1] * i0);
        *(__half2*)(o + (size_t)(b * TT + q0 + r0 + 8) * EE + h * 64 + d) =
            __floats2half2_rn(accO[ni][2] * i1, accO[ni][3] * i1);
    }
}

// ---------------- cross-entropy ----------------
__global__ void loss_row_kernel(const float* __restrict__ logits, const int* __restrict__ targets,
                                float* __restrict__ rowloss)
{
    int row = blockIdx.x;
    const float* lr = logits + (size_t)row * VV;
    __shared__ float red[256];
    int tid = threadIdx.x;

    float m = -1e30f;
    for (int i = tid; i < VV / 4; i += 256) {
        float4 v = ((const float4*)lr)[i];
        m = fmaxf(m, fmaxf(fmaxf(v.x, v.y), fmaxf(v.z, v.w)));
    }
    red[tid] = m; __syncthreads();
    for (int o = 128; o > 0; o >>= 1) { if (tid < o) red[tid] = fmaxf(red[tid], red[tid + o]); __syncthreads(); }
    m = red[0]; __syncthreads();

    float s = 0.f;
    for (int i = tid; i < VV / 4; i += 256) {
        float4 v = ((const float4*)lr)[i];
        s += fexp(v.x - m) + fexp(v.y - m) + fexp(v.z - m) + fexp(v.w - m);
    }
    red[tid] = s; __syncthreads();
    for (int o = 128; o > 0; o >>= 1) { if (tid < o) red[tid] += red[tid + o]; __syncthreads(); }

    if (tid == 0) {
        float lse = m + logf(red[0]);
        rowloss[row] = lse - lr[targets[row]];
    }
}

__global__ void loss_reduce_kernel(const float* __restrict__ rowloss, float* __restrict__ out)
{
    __shared__ float red[256];
    int tid = threadIdx.x;
    float s = 0.f;
    for (int i = tid; i < MROWS; i += 256) s += rowloss[i];
    red[tid] = s; __syncthreads();
    for (int o = 128; o > 0; o >>= 1) { if (tid < o) red[tid] += red[tid + o]; __syncthreads(); }
    if (tid == 0) out[0] = red[0] * (1.0f / MROWS);
}

// ---------------- host orchestration ----------------
#define SMEMG (6 * HTSZ * 2)   // 61440 bytes

extern "C" void kernel_launch(void* const* d_in, const int* in_sizes, int n_in,
                              void* d_out, int out_size)
{
    const int*   ctx  = (const int*)  d_in[0];
    const int*   tgt  = (const int*)  d_in[1];
    const float* tok  = (const float*)d_in[2];
    const float* pos  = (const float*)d_in[3];
    const float* Wq   = (const float*)d_in[4];
    const float* Wk   = (const float*)d_in[5];
    const float* Wv   = (const float*)d_in[6];
    const float* Wo   = (const float*)d_in[7];
    const float* bo   = (const float*)d_in[8];
    const float* ln1g = (const float*)d_in[9];
    const float* ln1b = (const float*)d_in[10];
    const float* ln2g = (const float*)d_in[11];
    const float* ln2b = (const float*)d_in[12];
    const float* W1   = (const float*)d_in[13];
    const float* b1   = (const float*)d_in[14];
    const float* W2   = (const float*)d_in[15];
    const float* b2   = (const float*)d_in[16];
    const float* lnfg = (const float*)d_in[17];
    const float* lnfb = (const float*)d_in[18];
    const float* Wlm  = (const float*)d_in[19];
    const float* blm  = (const float*)d_in[20];

    static float *px = nullptr, *prl;
    static __half *ph, *pq, *pk, *pv, *po, *pff;
    static __half *whq, *whk, *whv, *who, *wh1, *wh2, *whlm;
    if (!px) {
        cudaGetSymbolAddress((void**)&px,  g_x);
        cudaGetSymbolAddress((void**)&prl, g_rowloss);
        cudaGetSymbolAddress((void**)&ph,  g_h);
        cudaGetSymbolAddress((void**)&pq,  g_q);
        cudaGetSymbolAddress((void**)&pk,  g_k);
        cudaGetSymbolAddress((void**)&pv,  g_v);
        cudaGetSymbolAddress((void**)&po,  g_o);
        cudaGetSymbolAddress((void**)&pff, g_ff);
        cudaGetSymbolAddress((void**)&whq, g_whq);
        cudaGetSymbolAddress((void**)&whk, g_whk);
        cudaGetSymbolAddress((void**)&whv, g_whv);
        cudaGetSymbolAddress((void**)&who, g_who);
        cudaGetSymbolAddress((void**)&wh1, g_wh1);
        cudaGetSymbolAddress((void**)&wh2, g_wh2);
        cudaGetSymbolAddress((void**)&whlm, g_whlm);
        cudaFuncSetAttribute(hgemm_kernel, cudaFuncAttributeMaxDynamicSharedMemorySize, SMEMG);
    }
    float* out = (float*)d_out;

    // ---- weight transpose + fp16 conversion pre-pass ----
    dim3 tb(32, 8);
    transp_h<<<dim3(EE/32,  EE/32,  LL), tb>>>(Wq,  whq, EE,  EE);
    transp_h<<<dim3(EE/32,  EE/32,  LL), tb>>>(Wk,  whk, EE,  EE);
    transp_h<<<dim3(EE/32,  EE/32,  LL), tb>>>(Wv,  whv, EE,  EE);
    transp_h<<<dim3(EE/32,  EE/32,  LL), tb>>>(Wo,  who, EE,  EE);
    transp_h<<<dim3(FF_/32, EE/32,  LL), tb>>>(W1,  wh1, EE,  FF_);
    transp_h<<<dim3(EE/32,  FF_/32, LL), tb>>>(W2,  wh2, FF_, EE);
    transp_h<<<dim3(VV/32,  EE/32,  1),  tb>>>(Wlm, whlm, EE, VV);

    embed_kernel<<<MROWS, 256>>>(ctx, tok, pos, px);

    dim3 gQKV(24, 16);     // N=3072 (3 chunks of 1024)
    dim3 gEo (8, 16);      // N=1024
    dim3 gF1 (32, 16);     // N=4096
    dim3 gLM (250, 16);    // N=32000
    dim3 gFA (16, 32);

    for (int l = 0; l < LL; l++) {
        size_t oE = (size_t)l * EE * EE, oF = (size_t)l * EE * FF_;

        ln_kernel<<<MROWS, 256>>>(px, ln1g + l * EE, ln1b + l * EE, ph);

        hgemm_kernel<<<gQKV, 256, SMEMG>>>(ph, whq + oE, whk + oE, whv + oE, EE,
                                           nullptr, nullptr, pq, pk, pv, EE, 0, 1);

        flash_kernel<<<gFA, 128>>>(pq, pk, pv, po);

        hgemm_kernel<<<gEo, 256, SMEMG>>>(po, who + oE, who + oE, who + oE, EE,
                                          bo + l * EE, px, px, px, px, EE, 0, 0);

        ln_kernel<<<MROWS, 256>>>(px, ln2g + l * EE, ln2b + l * EE, ph);

        hgemm_kernel<<<gF1, 256, SMEMG>>>(ph, wh1 + oF, wh1 + oF, wh1 + oF, FF_,
                                          b1 + l * FF_, nullptr, pff, pff, pff, EE, 1, 1);

        hgemm_kernel<<<gEo, 256, SMEMG>>>(pff, wh2 + oF, wh2 + oF, wh2 + oF, EE,
                                          b2 + l * EE, px, px, px, px, FF_, 0, 0);
    }

    ln_kernel<<<MROWS, 256>>>(px, lnfg, lnfb, ph);
    hgemm_kernel<<<gLM, 256, SMEMG>>>(ph, whlm, whlm, whlm, VV,
                                      blm, nullptr, out, out, out, EE, 0, 0);

    if (out_size > MROWS * VV) {
        loss_row_kernel<<<MROWS, 256>>>(out, tgt, prl);
        loss_reduce_kernel<<<1, 256>>>(prl, out + (size_t)MROWS * VV);
    }
}

// round 7
// speedup vs baseline: 2.0808x; 1.3085x over previous
#include <cuda_runtime.h>
#include <cuda_fp16.h>
#include <math.h>
#include <stdint.h>

#define BB   2
#define TT   1024
#define EE   1024
#define HH   16
#define HD   64
#define LL   8
#define FF_  4096
#define VV   32000
#define MROWS (BB*TT)          // 2048

// ---------------- scratch ----------------
__device__ float  g_x  [MROWS*EE];            // fp32 residual
__device__ __half g_h  [MROWS*EE];            // LN outputs (GEMM A)
__device__ __half g_q  [MROWS*EE];
__device__ __half g_k  [MROWS*EE];
__device__ __half g_v  [MROWS*EE];
__device__ __half g_o  [MROWS*EE];
__device__ __half g_ff [MROWS*FF_];
__device__ float  g_rowloss[MROWS];
// fp16 weights, native [K][N] layout (converted, NOT transposed)
__device__ __half g_whq[LL*EE*EE];
__device__ __half g_whk[LL*EE*EE];
__device__ __half g_whv[LL*EE*EE];
__device__ __half g_who[LL*EE*EE];
__device__ __half g_wh1[LL*EE*FF_];
__device__ __half g_wh2[LL*FF_*EE];
__device__ __half g_whlm[(size_t)EE*VV];

// ---------------- helpers ----------------
__device__ __forceinline__ void mma_f16(float* d, const uint32_t* a, const uint32_t* b) {
    asm volatile(
        "mma.sync.aligned.m16n8k16.row.col.f32.f16.f16.f32 "
        "{%0,%1,%2,%3}, {%4,%5,%6,%7}, {%8,%9}, {%0,%1,%2,%3};"
        : "+f"(d[0]), "+f"(d[1]), "+f"(d[2]), "+f"(d[3])
        : "r"(a[0]), "r"(a[1]), "r"(a[2]), "r"(a[3]), "r"(b[0]), "r"(b[1]));
}
__device__ __forceinline__ void ldsm4(uint32_t* r, uint32_t addr) {
    asm volatile("ldmatrix.sync.aligned.m8n8.x4.shared.b16 {%0,%1,%2,%3}, [%4];"
        : "=r"(r[0]), "=r"(r[1]), "=r"(r[2]), "=r"(r[3]) : "r"(addr));
}
__device__ __forceinline__ void ldsm4t(uint32_t* r, uint32_t addr) {
    asm volatile("ldmatrix.sync.aligned.m8n8.x4.trans.shared.b16 {%0,%1,%2,%3}, [%4];"
        : "=r"(r[0]), "=r"(r[1]), "=r"(r[2]), "=r"(r[3]) : "r"(addr));
}
__device__ __forceinline__ uint32_t smem_u32(const void* p) {
    return (uint32_t)__cvta_generic_to_shared(p);
}
__device__ __forceinline__ void cp16h(__half* s, const __half* g) {
    uint32_t sa = smem_u32(s);
    asm volatile("cp.async.ca.shared.global [%0], [%1], 16;" :: "r"(sa), "l"(g));
}
#define CP_COMMIT() asm volatile("cp.async.commit_group;")

// fast exp on FMA/ALU pipes
__device__ __forceinline__ float fexp(float x) {
    float y = fmaxf(x * 1.44269504f, -126.0f);
    float t = y + 12582912.0f;
    int   e = __float_as_int(t);
    float r = t - 12582912.0f;
    float f = y - r;
    float p = 1.0f + f * (0.693147180f + f * (0.240226507f + f * (0.055504109f +
                     f * (0.009618130f + f * 0.001333356f))));
    return __int_as_float((e - 0x4B400000 + 127) << 23) * p;
}

// ---------------- streaming fp32 -> fp16 convert (coalesced, no transpose) ---------
__global__ void conv_h(const float4* __restrict__ in, uint2* __restrict__ out, int n4)
{
    int i = blockIdx.x * blockDim.x + threadIdx.x;
    int stride = gridDim.x * blockDim.x;
    for (; i < n4; i += stride) {
        float4 v = in[i];
        __half2 a = __floats2half2_rn(v.x, v.y);
        __half2 b = __floats2half2_rn(v.z, v.w);
        out[i] = make_uint2(*(uint32_t*)&a, *(uint32_t*)&b);
    }
}

// ---------------- embedding ----------------
__global__ void embed_kernel(const int* __restrict__ ctx, const float* __restrict__ tok,
                             const float* __restrict__ pos, float* __restrict__ x)
{
    int row = blockIdx.x;
    int t   = row % TT;
    int token = ctx[row];
    int tid = threadIdx.x;
    float4 te = ((const float4*)(tok + (size_t)token * EE))[tid];
    float4 pe = ((const float4*)(pos + (size_t)t * EE))[tid];
    ((float4*)(x + (size_t)row * EE))[tid] =
        make_float4(te.x + pe.x, te.y + pe.y, te.z + pe.z, te.w + pe.w);
}

// ---------------- layernorm: fp32 in, fp16 out ----------------
__global__ void ln_kernel(const float* __restrict__ x, const float* __restrict__ g,
                          const float* __restrict__ b, __half* __restrict__ y)
{
    int row = blockIdx.x, tid = threadIdx.x;
    float4 xv = ((const float4*)(x + (size_t)row * EE))[tid];
    float s = xv.x + xv.y + xv.z + xv.w;
    float q = xv.x * xv.x + xv.y * xv.y + xv.z * xv.z + xv.w * xv.w;
    #pragma unroll
    for (int o = 16; o; o >>= 1) {
        s += __shfl_xor_sync(0xffffffffu, s, o);
        q += __shfl_xor_sync(0xffffffffu, q, o);
    }
    __shared__ float ss[8], sq[8];
    int w = tid >> 5;
    if ((tid & 31) == 0) { ss[w] = s; sq[w] = q; }
    __syncthreads();
    if (tid < 32) {
        s = (tid < 8) ? ss[tid] : 0.f;
        q = (tid < 8) ? sq[tid] : 0.f;
        #pragma unroll
        for (int o = 4; o; o >>= 1) {
            s += __shfl_xor_sync(0xffffffffu, s, o);
            q += __shfl_xor_sync(0xffffffffu, q, o);
        }
        if (tid == 0) { ss[0] = s; sq[0] = q; }
    }
    __syncthreads();
    float mu  = ss[0] * (1.0f / EE);
    float var = fmaxf(sq[0] * (1.0f / EE) - mu * mu, 0.f);
    float rs  = rsqrtf(var + 1e-5f);
    float4 gv = ((const float4*)g)[tid], bv = ((const float4*)b)[tid];
    __half2 h0 = __floats2half2_rn((xv.x - mu) * rs * gv.x + bv.x,
                                   (xv.y - mu) * rs * gv.y + bv.y);
    __half2 h1 = __floats2half2_rn((xv.z - mu) * rs * gv.z + bv.z,
                                   (xv.w - mu) * rs * gv.w + bv.w);
    *(uint2*)(y + (size_t)row * EE + tid * 4) = make_uint2(*(uint32_t*)&h0, *(uint32_t*)&h1);
}

// ---------------- fp16 GEMM: 128x128 CTA tile, 8 warps, 32x64 warp tiles ------------
// A[M,K] fp16; W[K,N] fp16 native layout. B frags via ldmatrix.trans.
// 3-stage cp.async. Up to 3 weight/output chunks of width wN.
#define HSTR 40
#define ASZH (128*HSTR)
#define BSTRH 136
#define BSZH (32*BSTRH)

__global__ __launch_bounds__(256, 2) void hgemm_kernel(
    const __half* __restrict__ A,
    const __half* __restrict__ w0, const __half* __restrict__ w1, const __half* __restrict__ w2,
    int wN,
    const float* __restrict__ bias, const float* __restrict__ res,
    void* c0, void* c1, void* c2,
    int K, int relu, int outHalf)
{
    extern __shared__ __half sm[];
    __half* As = sm;                  // 3 stages [128][40]
    __half* Bs = sm + 3 * ASZH;       // 3 stages [32][136]  ([k][n])

    int tid = threadIdx.x;
    int warp = tid >> 5, lane = tid & 31;
    int g = lane >> 2, t = lane & 3;
    int lrow = lane & 15, lk = (lane >> 4) * 8;
    int wm = (warp & 3) * 32;
    int wn = (warp >> 2) * 64;
    int row0 = blockIdx.y * 128;
    int col0 = blockIdx.x * 128;

    int chunk = col0 / wN;
    int lcol0 = col0 - chunk * wN;
    const __half* W = (chunk == 0) ? w0 : (chunk == 1 ? w1 : w2);
    void* C = (chunk == 0) ? c0 : (chunk == 1 ? c1 : c2);
    const __half* Ab = A + (size_t)row0 * K;
    const __half* Wb = W + lcol0;

    float acc[2][8][4] = {};

    auto issue = [&](int st, int k0) {
        __half* as = As + st * ASZH;
        __half* bs = Bs + st * BSZH;
        #pragma unroll
        for (int i = 0; i < 2; i++) {
            int idx = tid + i * 256;
            int m = idx >> 2, kq = (idx & 3) * 8;
            cp16h(&as[m * HSTR + kq], Ab + (size_t)m * K + k0 + kq);
            int kr = idx >> 4, nq = (idx & 15) * 8;
            cp16h(&bs[kr * BSTRH + nq], Wb + (size_t)(k0 + kr) * wN + nq);
        }
    };
    auto compute = [&](int st) {
        uint32_t asb = smem_u32(As + st * ASZH);
        uint32_t bsb = smem_u32(Bs + st * BSZH);
        #pragma unroll
        for (int kk = 0; kk < 2; kk++) {
            int kb = kk * 16;
            uint32_t af[2][4], bf[8][2];
            #pragma unroll
            for (int mi = 0; mi < 2; mi++)
                ldsm4(af[mi], asb + ((wm + mi * 16 + lrow) * HSTR + kb + lk) * 2);
            #pragma unroll
            for (int nj = 0; nj < 4; nj++) {
                uint32_t r[4];
                ldsm4t(r, bsb + ((kb + lrow) * BSTRH + wn + nj * 16 + lk) * 2);
                bf[2*nj][0]   = r[0]; bf[2*nj][1]   = r[1];
                bf[2*nj+1][0] = r[2]; bf[2*nj+1][1] = r[3];
            }
            #pragma unroll
            for (int mi = 0; mi < 2; mi++)
                #pragma unroll
                for (int ni = 0; ni < 8; ni++)
                    mma_f16(acc[mi][ni], af[mi], bf[ni]);
        }
    };

    issue(0, 0);  CP_COMMIT();
    issue(1, 32); CP_COMMIT();
    int s = 0;
    for (int k0 = 0; k0 < K; k0 += 32) {
        asm volatile("cp.async.wait_group 1;");
        __syncthreads();
        int kpf = k0 + 64;
        if (kpf < K) issue((s + 2) % 3, kpf);
        CP_COMMIT();
        compute(s);
        s = (s + 1) % 3;
        __syncthreads();
    }

    #pragma unroll
    for (int mi = 0; mi < 2; mi++) {
        int r = row0 + wm + mi * 16 + g;
        #pragma unroll
        for (int ni = 0; ni < 8; ni++) {
            int c = lcol0 + wn + ni * 8 + t * 2;
            float v0 = acc[mi][ni][0], v1 = acc[mi][ni][1];
            float v2 = acc[mi][ni][2], v3 = acc[mi][ni][3];
            if (bias) { float b0 = bias[c], b1 = bias[c + 1]; v0 += b0; v1 += b1; v2 += b0; v3 += b1; }
            if (res) {
                v0 += res[(size_t)r * wN + c];       v1 += res[(size_t)r * wN + c + 1];
                v2 += res[(size_t)(r + 8) * wN + c]; v3 += res[(size_t)(r + 8) * wN + c + 1];
            }
            if (relu) { v0 = fmaxf(v0, 0.f); v1 = fmaxf(v1, 0.f); v2 = fmaxf(v2, 0.f); v3 = fmaxf(v3, 0.f); }
            if (outHalf) {
                __half* Ch = (__half*)C;
                *(__half2*)&Ch[(size_t)r * wN + c]       = __floats2half2_rn(v0, v1);
                *(__half2*)&Ch[(size_t)(r + 8) * wN + c] = __floats2half2_rn(v2, v3);
            } else {
                float* Cf = (float*)C;
                *(float2*)&Cf[(size_t)r * wN + c]       = make_float2(v0, v1);
                *(float2*)&Cf[(size_t)(r + 8) * wN + c] = make_float2(v2, v3);
            }
        }
    }
}

// ---------------- fused flash attention, fp16 mma + ldmatrix (causal) ---------------
#define FSTR 72
__global__ __launch_bounds__(128, 3) void flash_kernel(
    const __half* __restrict__ q, const __half* __restrict__ k,
    const __half* __restrict__ v, __half* __restrict__ o)
{
    __shared__ __half Qs[64 * FSTR];
    __shared__ __half Ks[64 * FSTR];
    __shared__ __half Ps[64 * FSTR];
    __shared__ __half Vs[64 * FSTR];   // row-major [key][d]

    int qt = blockIdx.x, bh = blockIdx.y;
    int b = bh >> 4, h = bh & 15;
    int q0 = qt * 64;

    int tid = threadIdx.x;
    int warp = tid >> 5, lane = tid & 31;
    int g = lane >> 2, t = lane & 3;
    int lrow = lane & 15, lk = (lane >> 4) * 8;
    int wq = warp * 16;
    int r0 = wq + g;

    uint32_t qsb = smem_u32(Qs), ksb = smem_u32(Ks), psb = smem_u32(Ps), vsb = smem_u32(Vs);

    // load Q tile (64x64 halfs)
    #pragma unroll
    for (int i = 0; i < 4; i++) {
        int idx = tid + i * 128;
        int r = idx >> 3, dq = (idx & 7) * 8;
        *(uint4*)&Qs[r * FSTR + dq] =
            *(const uint4*)(q + (size_t)(b * TT + q0 + r) * EE + h * 64 + dq);
    }

    float accO[8][4] = {};
    float mr0 = -1e30f, mr1 = -1e30f, lr0 = 0.f, lr1 = 0.f;
    const float scale = 0.03125f;

    for (int kt = 0; kt <= qt; kt++) {
        int k0 = kt * 64;
        __syncthreads();
        #pragma unroll
        for (int i = 0; i < 4; i++) {
            int idx = tid + i * 128;
            int r = idx >> 3, dq = (idx & 7) * 8;
            *(uint4*)&Ks[r * FSTR + dq] =
                *(const uint4*)(k + (size_t)(b * TT + k0 + r) * EE + h * 64 + dq);
            *(uint4*)&Vs[r * FSTR + dq] =
                *(const uint4*)(v + (size_t)(b * TT + k0 + r) * EE + h * 64 + dq);
        }
        __syncthreads();

        // S = Q K^T : 4 k16 steps over d; K rows are the B operand (non-trans ldmatrix)
        float accS[8][4] = {};
        #pragma unroll
        for (int kb = 0; kb < 64; kb += 16) {
            uint32_t af[4];
            ldsm4(af, qsb + ((wq + lrow) * FSTR + kb + lk) * 2);
            #pragma unroll
            for (int nj = 0; nj < 4; nj++) {
                uint32_t r[4];
                ldsm4(r, ksb + ((nj * 16 + lrow) * FSTR + kb + lk) * 2);
                uint32_t bf0[2] = { r[0], r[2] };
                uint32_t bf1[2] = { r[1], r[3] };
                mma_f16(accS[2*nj],   af, bf0);
                mma_f16(accS[2*nj+1], af, bf1);
            }
        }

        bool diag = (kt == qt);
        #pragma unroll
        for (int ni = 0; ni < 8; ni++) {
            int c = ni * 8 + t * 2;
            accS[ni][0] *= scale; accS[ni][1] *= scale;
            accS[ni][2] *= scale; accS[ni][3] *= scale;
            if (diag) {
                if (c     > r0)     accS[ni][0] = -1e30f;
                if (c + 1 > r0)     accS[ni][1] = -1e30f;
                if (c     > r0 + 8) accS[ni][2] = -1e30f;
                if (c + 1 > r0 + 8) accS[ni][3] = -1e30f;
            }
        }

        float m0 = -1e30f, m1 = -1e30f;
        #pragma unroll
        for (int ni = 0; ni < 8; ni++) {
            m0 = fmaxf(m0, fmaxf(accS[ni][0], accS[ni][1]));
            m1 = fmaxf(m1, fmaxf(accS[ni][2], accS[ni][3]));
        }
        m0 = fmaxf(m0, __shfl_xor_sync(0xffffffffu, m0, 1));
        m0 = fmaxf(m0, __shfl_xor_sync(0xffffffffu, m0, 2));
        m1 = fmaxf(m1, __shfl_xor_sync(0xffffffffu, m1, 1));
        m1 = fmaxf(m1, __shfl_xor_sync(0xffffffffu, m1, 2));

        float mn0 = fmaxf(mr0, m0), mn1 = fmaxf(mr1, m1);
        float a0 = fexp(mr0 - mn0), a1 = fexp(mr1 - mn1);

        float s0 = 0.f, s1 = 0.f;
        #pragma unroll
        for (int ni = 0; ni < 8; ni++) {
            accS[ni][0] = fexp(accS[ni][0] - mn0);
            accS[ni][1] = fexp(accS[ni][1] - mn0);
            accS[ni][2] = fexp(accS[ni][2] - mn1);
            accS[ni][3] = fexp(accS[ni][3] - mn1);
            s0 += accS[ni][0] + accS[ni][1];
            s1 += accS[ni][2] + accS[ni][3];
        }
        s0 += __shfl_xor_sync(0xffffffffu, s0, 1);
        s0 += __shfl_xor_sync(0xffffffffu, s0, 2);
        s1 += __shfl_xor_sync(0xffffffffu, s1, 1);
        s1 += __shfl_xor_sync(0xffffffffu, s1, 2);

        lr0 = lr0 * a0 + s0;
        lr1 = lr1 * a1 + s1;
        mr0 = mn0; mr1 = mn1;

        #pragma unroll
        for (int ni = 0; ni < 8; ni++) {
            accO[ni][0] *= a0; accO[ni][1] *= a0;
            accO[ni][2] *= a1; accO[ni][3] *= a1;
        }

        // P -> smem (fp16), own rows only
        #pragma unroll
        for (int ni = 0; ni < 8; ni++) {
            int c = ni * 8 + 2 * t;
            *(__half2*)&Ps[r0 * FSTR + c]       = __floats2half2_rn(accS[ni][0], accS[ni][1]);
            *(__half2*)&Ps[(r0 + 8) * FSTR + c] = __floats2half2_rn(accS[ni][2], accS[ni][3]);
        }
        __syncwarp();

        // O += P V : keys are k dim; V row-major [key][d] -> B via ldmatrix.trans
        #pragma unroll
        for (int kb = 0; kb < 64; kb += 16) {
            uint32_t af[4];
            ldsm4(af, psb + ((wq + lrow) * FSTR + kb + lk) * 2);
            #pragma unroll
            for (int nj = 0; nj < 4; nj++) {
                uint32_t r[4];
                ldsm4t(r, vsb + ((kb + lrow) * FSTR + nj * 16 + lk) * 2);
                uint32_t bf0[2] = { r[0], r[1] };
                uint32_t bf1[2] = { r[2], r[3] };
                mma_f16(accO[2*nj],   af, bf0);
                mma_f16(accO[2*nj+1], af, bf1);
            }
        }
    }

    float i0 = 1.f / lr0, i1 = 1.f / lr1;
    #pragma unroll
    for (int ni = 0; ni < 8; ni++) {
        int d = ni * 8 + 2 * t;
        *(__half2*)(o + (size_t)(b * TT + q0 + r0) * EE + h * 64 + d) =
            __floats2half2_rn(accO[ni][0] * i0, accO[ni][1] * i0);
        *(__half2*)(o + (size_t)(b * TT + q0 + r0 + 8) * EE + h * 64 + d) =
            __floats2half2_rn(accO[ni][2] * i1, accO[ni][3] * i1);
    }
}

// ---------------- cross-entropy ----------------
__global__ void loss_row_kernel(const float* __restrict__ logits, const int* __restrict__ targets,
                                float* __restrict__ rowloss)
{
    int row = blockIdx.x;
    const float* lr = logits + (size_t)row * VV;
    __shared__ float red[256];
    int tid = threadIdx.x;

    float m = -1e30f;
    for (int i = tid; i < VV / 4; i += 256) {
        float4 v = ((const float4*)lr)[i];
        m = fmaxf(m, fmaxf(fmaxf(v.x, v.y), fmaxf(v.z, v.w)));
    }
    red[tid] = m; __syncthreads();
    for (int o = 128; o > 0; o >>= 1) { if (tid < o) red[tid] = fmaxf(red[tid], red[tid + o]); __syncthreads(); }
    m = red[0]; __syncthreads();

    float s = 0.f;
    for (int i = tid; i < VV / 4; i += 256) {
        float4 v = ((const float4*)lr)[i];
        s += fexp(v.x - m) + fexp(v.y - m) + fexp(v.z - m) + fexp(v.w - m);
    }
    red[tid] = s; __syncthreads();
    for (int o = 128; o > 0; o >>= 1) { if (tid < o) red[tid] += red[tid + o]; __syncthreads(); }

    if (tid == 0) {
        float lse = m + logf(red[0]);
        rowloss[row] = lse - lr[targets[row]];
    }
}

__global__ void loss_reduce_kernel(const float* __restrict__ rowloss, float* __restrict__ out)
{
    __shared__ float red[256];
    int tid = threadIdx.x;
    float s = 0.f;
    for (int i = tid; i < MROWS; i += 256) s += rowloss[i];
    red[tid] = s; __syncthreads();
    for (int o = 128; o > 0; o >>= 1) { if (tid < o) red[tid] += red[tid + o]; __syncthreads(); }
    if (tid == 0) out[0] = red[0] * (1.0f / MROWS);
}

// ---------------- host orchestration ----------------
#define SMEMG ((3 * (ASZH + BSZH)) * 2)   // 56832 bytes

extern "C" void kernel_launch(void* const* d_in, const int* in_sizes, int n_in,
                              void* d_out, int out_size)
{
    const int*   ctx  = (const int*)  d_in[0];
    const int*   tgt  = (const int*)  d_in[1];
    const float* tok  = (const float*)d_in[2];
    const float* pos  = (const float*)d_in[3];
    const float* Wq   = (const float*)d_in[4];
    const float* Wk   = (const float*)d_in[5];
    const float* Wv   = (const float*)d_in[6];
    const float* Wo   = (const float*)d_in[7];
    const float* bo   = (const float*)d_in[8];
    const float* ln1g = (const float*)d_in[9];
    const float* ln1b = (const float*)d_in[10];
    const float* ln2g = (const float*)d_in[11];
    const float* ln2b = (const float*)d_in[12];
    const float* W1   = (const float*)d_in[13];
    const float* b1   = (const float*)d_in[14];
    const float* W2   = (const float*)d_in[15];
    const float* b2   = (const float*)d_in[16];
    const float* lnfg = (const float*)d_in[17];
    const float* lnfb = (const float*)d_in[18];
    const float* Wlm  = (const float*)d_in[19];
    const float* blm  = (const float*)d_in[20];

    static float *px = nullptr, *prl;
    static __half *ph, *pq, *pk, *pv, *po, *pff;
    static __half *whq, *whk, *whv, *who, *wh1, *wh2, *whlm;
    if (!px) {
        cudaGetSymbolAddress((void**)&px,  g_x);
        cudaGetSymbolAddress((void**)&prl, g_rowloss);
        cudaGetSymbolAddress((void**)&ph,  g_h);
        cudaGetSymbolAddress((void**)&pq,  g_q);
        cudaGetSymbolAddress((void**)&pk,  g_k);
        cudaGetSymbolAddress((void**)&pv,  g_v);
        cudaGetSymbolAddress((void**)&po,  g_o);
        cudaGetSymbolAddress((void**)&pff, g_ff);
        cudaGetSymbolAddress((void**)&whq, g_whq);
        cudaGetSymbolAddress((void**)&whk, g_whk);
        cudaGetSymbolAddress((void**)&whv, g_whv);
        cudaGetSymbolAddress((void**)&who, g_who);
        cudaGetSymbolAddress((void**)&wh1, g_wh1);
        cudaGetSymbolAddress((void**)&wh2, g_wh2);
        cudaGetSymbolAddress((void**)&whlm, g_whlm);
        cudaFuncSetAttribute(hgemm_kernel, cudaFuncAttributeMaxDynamicSharedMemorySize, SMEMG);
    }
    float* out = (float*)d_out;

    // ---- streaming fp32->fp16 conversion pre-pass (coalesced) ----
    conv_h<<<4096, 256>>>((const float4*)Wq,  (uint2*)whq,  LL*EE*EE/4);
    conv_h<<<4096, 256>>>((const float4*)Wk,  (uint2*)whk,  LL*EE*EE/4);
    conv_h<<<4096, 256>>>((const float4*)Wv,  (uint2*)whv,  LL*EE*EE/4);
    conv_h<<<4096, 256>>>((const float4*)Wo,  (uint2*)who,  LL*EE*EE/4);
    conv_h<<<8192, 256>>>((const float4*)W1,  (uint2*)wh1,  LL*EE*FF_/4);
    conv_h<<<8192, 256>>>((const float4*)W2,  (uint2*)wh2,  LL*FF_*EE/4);
    conv_h<<<8192, 256>>>((const float4*)Wlm, (uint2*)whlm, EE*VV/4);

    embed_kernel<<<MROWS, 256>>>(ctx, tok, pos, px);

    dim3 gQKV(24, 16);     // N=3072 (3 chunks of 1024)
    dim3 gEo (8, 16);      // N=1024
    dim3 gF1 (32, 16);     // N=4096
    dim3 gLM (250, 16);    // N=32000
    dim3 gFA (16, 32);

    for (int l = 0; l < LL; l++) {
        size_t oE = (size_t)l * EE * EE, oF = (size_t)l * EE * FF_;

        ln_kernel<<<MROWS, 256>>>(px, ln1g + l * EE, ln1b + l * EE, ph);

        hgemm_kernel<<<gQKV, 256, SMEMG>>>(ph, whq + oE, whk + oE, whv + oE, EE,
                                           nullptr, nullptr, pq, pk, pv, EE, 0, 1);

        flash_kernel<<<gFA, 128>>>(pq, pk, pv, po);

        hgemm_kernel<<<gEo, 256, SMEMG>>>(po, who + oE, who + oE, who + oE, EE,
                                          bo + l * EE, px, px, px, px, EE, 0, 0);

        ln_kernel<<<MROWS, 256>>>(px, ln2g + l * EE, ln2b + l * EE, ph);

        hgemm_kernel<<<gF1, 256, SMEMG>>>(ph, wh1 + oF, wh1 + oF, wh1 + oF, FF_,
                                          b1 + l * FF_, nullptr, pff, pff, pff, EE, 1, 1);

        hgemm_kernel<<<gEo, 256, SMEMG>>>(pff, wh2 + oF, wh2 + oF, wh2 + oF, EE,
                                          b2 + l * EE, px, px, px, px, FF_, 0, 0);
    }

    ln_kernel<<<MROWS, 256>>>(px, lnfg, lnfb, ph);
    hgemm_kernel<<<gLM, 256, SMEMG>>>(ph, whlm, whlm, whlm, VV,
                                      blm, nullptr, out, out, out, EE, 0, 0);

    if (out_size > MROWS * VV) {
        loss_row_kernel<<<MROWS, 256>>>(out, tgt, prl);
        loss_reduce_kernel<<<1, 256>>>(prl, out + (size_t)MROWS * VV);
    }
}

// round 8
// speedup vs baseline: 2.0964x; 1.0075x over previous
#include <cuda_runtime.h>
#include <cuda_fp16.h>
#include <math.h>
#include <stdint.h>

#define BB   2
#define TT   1024
#define EE   1024
#define HH   16
#define HD   64
#define LL   8
#define FF_  4096
#define VV   32000
#define MROWS (BB*TT)          // 2048

// ---------------- scratch ----------------
__device__ float  g_x  [MROWS*EE];            // fp32 residual
__device__ __half g_h  [MROWS*EE];            // LN outputs (GEMM A)
__device__ __half g_q  [MROWS*EE];
__device__ __half g_k  [MROWS*EE];
__device__ __half g_v  [MROWS*EE];
__device__ __half g_o  [MROWS*EE];
__device__ __half g_ff [MROWS*FF_];
__device__ float  g_rowloss[MROWS];
// fp16 weights, native [K][N] layout
__device__ __half g_whq[LL*EE*EE];
__device__ __half g_whk[LL*EE*EE];
__device__ __half g_whv[LL*EE*EE];
__device__ __half g_who[LL*EE*EE];
__device__ __half g_wh1[LL*EE*FF_];
__device__ __half g_wh2[LL*FF_*EE];
__device__ __half g_whlm[(size_t)EE*VV];

// ---------------- helpers ----------------
__device__ __forceinline__ void mma_f16(float* d, const uint32_t* a, const uint32_t* b) {
    asm volatile(
        "mma.sync.aligned.m16n8k16.row.col.f32.f16.f16.f32 "
        "{%0,%1,%2,%3}, {%4,%5,%6,%7}, {%8,%9}, {%0,%1,%2,%3};"
        : "+f"(d[0]), "+f"(d[1]), "+f"(d[2]), "+f"(d[3])
        : "r"(a[0]), "r"(a[1]), "r"(a[2]), "r"(a[3]), "r"(b[0]), "r"(b[1]));
}
__device__ __forceinline__ void ldsm4(uint32_t* r, uint32_t addr) {
    asm volatile("ldmatrix.sync.aligned.m8n8.x4.shared.b16 {%0,%1,%2,%3}, [%4];"
        : "=r"(r[0]), "=r"(r[1]), "=r"(r[2]), "=r"(r[3]) : "r"(addr));
}
__device__ __forceinline__ void ldsm4t(uint32_t* r, uint32_t addr) {
    asm volatile("ldmatrix.sync.aligned.m8n8.x4.trans.shared.b16 {%0,%1,%2,%3}, [%4];"
        : "=r"(r[0]), "=r"(r[1]), "=r"(r[2]), "=r"(r[3]) : "r"(addr));
}
__device__ __forceinline__ uint32_t smem_u32(const void* p) {
    return (uint32_t)__cvta_generic_to_shared(p);
}
__device__ __forceinline__ void cp16h(__half* s, const __half* g) {
    uint32_t sa = smem_u32(s);
    asm volatile("cp.async.ca.shared.global [%0], [%1], 16;" :: "r"(sa), "l"(g));
}
#define CP_COMMIT() asm volatile("cp.async.commit_group;")

// fast exp on FMA/ALU pipes
__device__ __forceinline__ float fexp(float x) {
    float y = fmaxf(x * 1.44269504f, -126.0f);
    float t = y + 12582912.0f;
    int   e = __float_as_int(t);
    float r = t - 12582912.0f;
    float f = y - r;
    float p = 1.0f + f * (0.693147180f + f * (0.240226507f + f * (0.055504109f +
                     f * (0.009618130f + f * 0.001333356f))));
    return __int_as_float((e - 0x4B400000 + 127) << 23) * p;
}

// ---------------- streaming fp32 -> fp16 convert ----------------
__global__ void conv_h(const float4* __restrict__ in, uint2* __restrict__ out, int n4)
{
    int i = blockIdx.x * blockDim.x + threadIdx.x;
    int stride = gridDim.x * blockDim.x;
    for (; i < n4; i += stride) {
        float4 v = in[i];
        __half2 a = __floats2half2_rn(v.x, v.y);
        __half2 b = __floats2half2_rn(v.z, v.w);
        out[i] = make_uint2(*(uint32_t*)&a, *(uint32_t*)&b);
    }
}

// ---------------- embedding ----------------
__global__ void embed_kernel(const int* __restrict__ ctx, const float* __restrict__ tok,
                             const float* __restrict__ pos, float* __restrict__ x)
{
    int row = blockIdx.x;
    int t   = row % TT;
    int token = ctx[row];
    int tid = threadIdx.x;
    float4 te = ((const float4*)(tok + (size_t)token * EE))[tid];
    float4 pe = ((const float4*)(pos + (size_t)t * EE))[tid];
    ((float4*)(x + (size_t)row * EE))[tid] =
        make_float4(te.x + pe.x, te.y + pe.y, te.z + pe.z, te.w + pe.w);
}

// ---------------- layernorm: fp32 in, fp16 out ----------------
__global__ void ln_kernel(const float* __restrict__ x, const float* __restrict__ g,
                          const float* __restrict__ b, __half* __restrict__ y)
{
    int row = blockIdx.x, tid = threadIdx.x;
    float4 xv = ((const float4*)(x + (size_t)row * EE))[tid];
    float s = xv.x + xv.y + xv.z + xv.w;
    float q = xv.x * xv.x + xv.y * xv.y + xv.z * xv.z + xv.w * xv.w;
    #pragma unroll
    for (int o = 16; o; o >>= 1) {
        s += __shfl_xor_sync(0xffffffffu, s, o);
        q += __shfl_xor_sync(0xffffffffu, q, o);
    }
    __shared__ float ss[8], sq[8];
    int w = tid >> 5;
    if ((tid & 31) == 0) { ss[w] = s; sq[w] = q; }
    __syncthreads();
    if (tid < 32) {
        s = (tid < 8) ? ss[tid] : 0.f;
        q = (tid < 8) ? sq[tid] : 0.f;
        #pragma unroll
        for (int o = 4; o; o >>= 1) {
            s += __shfl_xor_sync(0xffffffffu, s, o);
            q += __shfl_xor_sync(0xffffffffu, q, o);
        }
        if (tid == 0) { ss[0] = s; sq[0] = q; }
    }
    __syncthreads();
    float mu  = ss[0] * (1.0f / EE);
    float var = fmaxf(sq[0] * (1.0f / EE) - mu * mu, 0.f);
    float rs  = rsqrtf(var + 1e-5f);
    float4 gv = ((const float4*)g)[tid], bv = ((const float4*)b)[tid];
    __half2 h0 = __floats2half2_rn((xv.x - mu) * rs * gv.x + bv.x,
                                   (xv.y - mu) * rs * gv.y + bv.y);
    __half2 h1 = __floats2half2_rn((xv.z - mu) * rs * gv.z + bv.z,
                                   (xv.w - mu) * rs * gv.w + bv.w);
    *(uint2*)(y + (size_t)row * EE + tid * 4) = make_uint2(*(uint32_t*)&h0, *(uint32_t*)&h1);
}

// ---------------- fp16 GEMM: 128x128 CTA tile, 8 warps, 32x64 warp tiles ------------
// blockIdx.x = M tile (fastest), blockIdx.y = N tile  -> L2 reuse of B across row blocks.
// 4-stage cp.async pipeline, ONE __syncthreads per chunk.
#define HSTR 40
#define ASZH (128*HSTR)
#define BSTRH 136
#define BSZH (32*BSTRH)
#define NSTG 4

__global__ __launch_bounds__(256, 2) void hgemm_kernel(
    const __half* __restrict__ A,
    const __half* __restrict__ w0, const __half* __restrict__ w1, const __half* __restrict__ w2,
    int wN,
    const float* __restrict__ bias, const float* __restrict__ res,
    void* c0, void* c1, void* c2,
    int K, int relu, int outHalf)
{
    extern __shared__ __half sm[];
    __half* As = sm;                     // NSTG stages [128][40]
    __half* Bs = sm + NSTG * ASZH;       // NSTG stages [32][136]

    int tid = threadIdx.x;
    int warp = tid >> 5, lane = tid & 31;
    int g = lane >> 2, t = lane & 3;
    int lrow = lane & 15, lk = (lane >> 4) * 8;
    int wm = (warp & 3) * 32;
    int wn = (warp >> 2) * 64;
    int row0 = blockIdx.x * 128;
    int col0 = blockIdx.y * 128;

    int chunk = col0 / wN;
    int lcol0 = col0 - chunk * wN;
    const __half* W = (chunk == 0) ? w0 : (chunk == 1 ? w1 : w2);
    void* C = (chunk == 0) ? c0 : (chunk == 1 ? c1 : c2);
    const __half* Ab = A + (size_t)row0 * K;
    const __half* Wb = W + lcol0;

    float acc[2][8][4] = {};

    auto issue = [&](int st, int k0) {
        __half* as = As + st * ASZH;
        __half* bs = Bs + st * BSZH;
        #pragma unroll
        for (int i = 0; i < 2; i++) {
            int idx = tid + i * 256;
            int m = idx >> 2, kq = (idx & 3) * 8;
            cp16h(&as[m * HSTR + kq], Ab + (size_t)m * K + k0 + kq);
            int kr = idx >> 4, nq = (idx & 15) * 8;
            cp16h(&bs[kr * BSTRH + nq], Wb + (size_t)(k0 + kr) * wN + nq);
        }
    };
    auto compute = [&](int st) {
        uint32_t asb = smem_u32(As + st * ASZH);
        uint32_t bsb = smem_u32(Bs + st * BSZH);
        #pragma unroll
        for (int kk = 0; kk < 2; kk++) {
            int kb = kk * 16;
            uint32_t af[2][4], bf[8][2];
            #pragma unroll
            for (int mi = 0; mi < 2; mi++)
                ldsm4(af[mi], asb + ((wm + mi * 16 + lrow) * HSTR + kb + lk) * 2);
            #pragma unroll
            for (int nj = 0; nj < 4; nj++) {
                uint32_t r[4];
                ldsm4t(r, bsb + ((kb + lrow) * BSTRH + wn + nj * 16 + lk) * 2);
                bf[2*nj][0]   = r[0]; bf[2*nj][1]   = r[1];
                bf[2*nj+1][0] = r[2]; bf[2*nj+1][1] = r[3];
            }
            #pragma unroll
            for (int mi = 0; mi < 2; mi++)
                #pragma unroll
                for (int ni = 0; ni < 8; ni++)
                    mma_f16(acc[mi][ni], af[mi], bf[ni]);
        }
    };

    int nks = K >> 5;
    issue(0, 0);  CP_COMMIT();
    issue(1, 32); CP_COMMIT();
    issue(2, 64); CP_COMMIT();
    for (int ks = 0; ks < nks; ks++) {
        int s = ks & (NSTG - 1);
        asm volatile("cp.async.wait_group 2;");
        __syncthreads();
        int kpf = ks + 3;
        if (kpf < nks) issue(kpf & (NSTG - 1), kpf * 32);
        CP_COMMIT();
        compute(s);
    }

    #pragma unroll
    for (int mi = 0; mi < 2; mi++) {
        int r = row0 + wm + mi * 16 + g;
        #pragma unroll
        for (int ni = 0; ni < 8; ni++) {
            int c = lcol0 + wn + ni * 8 + t * 2;
            float v0 = acc[mi][ni][0], v1 = acc[mi][ni][1];
            float v2 = acc[mi][ni][2], v3 = acc[mi][ni][3];
            if (bias) { float b0 = bias[c], b1 = bias[c + 1]; v0 += b0; v1 += b1; v2 += b0; v3 += b1; }
            if (res) {
                v0 += res[(size_t)r * wN + c];       v1 += res[(size_t)r * wN + c + 1];
                v2 += res[(size_t)(r + 8) * wN + c]; v3 += res[(size_t)(r + 8) * wN + c + 1];
            }
            if (relu) { v0 = fmaxf(v0, 0.f); v1 = fmaxf(v1, 0.f); v2 = fmaxf(v2, 0.f); v3 = fmaxf(v3, 0.f); }
            if (outHalf) {
                __half* Ch = (__half*)C;
                *(__half2*)&Ch[(size_t)r * wN + c]       = __floats2half2_rn(v0, v1);
                *(__half2*)&Ch[(size_t)(r + 8) * wN + c] = __floats2half2_rn(v2, v3);
            } else {
                float* Cf = (float*)C;
                *(float2*)&Cf[(size_t)r * wN + c]       = make_float2(v0, v1);
                *(float2*)&Cf[(size_t)(r + 8) * wN + c] = make_float2(v2, v3);
            }
        }
    }
}

// ---------------- fused flash attention, fp16 mma + ldmatrix (causal) ---------------
// grid (bh, qtile); heaviest q tiles scheduled FIRST (qt reversed).
#define FSTR 72
__global__ __launch_bounds__(128, 3) void flash_kernel(
    const __half* __restrict__ q, const __half* __restrict__ k,
    const __half* __restrict__ v, __half* __restrict__ o)
{
    __shared__ __half Qs[64 * FSTR];
    __shared__ __half Ks[64 * FSTR];
    __shared__ __half Ps[64 * FSTR];
    __shared__ __half Vs[64 * FSTR];

    int bh = blockIdx.x;
    int qt = (int)gridDim.y - 1 - (int)blockIdx.y;   // heavy tiles first
    int b = bh >> 4, h = bh & 15;
    int q0 = qt * 64;

    int tid = threadIdx.x;
    int warp = tid >> 5, lane = tid & 31;
    int g = lane >> 2, t = lane & 3;
    int lrow = lane & 15, lk = (lane >> 4) * 8;
    int wq = warp * 16;
    int r0 = wq + g;

    uint32_t qsb = smem_u32(Qs), ksb = smem_u32(Ks), psb = smem_u32(Ps), vsb = smem_u32(Vs);

    #pragma unroll
    for (int i = 0; i < 4; i++) {
        int idx = tid + i * 128;
        int r = idx >> 3, dq = (idx & 7) * 8;
        *(uint4*)&Qs[r * FSTR + dq] =
            *(const uint4*)(q + (size_t)(b * TT + q0 + r) * EE + h * 64 + dq);
    }

    float accO[8][4] = {};
    float mr0 = -1e30f, mr1 = -1e30f, lr0 = 0.f, lr1 = 0.f;
    const float scale = 0.03125f;

    for (int kt = 0; kt <= qt; kt++) {
        int k0 = kt * 64;
        __syncthreads();
        #pragma unroll
        for (int i = 0; i < 4; i++) {
            int idx = tid + i * 128;
            int r = idx >> 3, dq = (idx & 7) * 8;
            *(uint4*)&Ks[r * FSTR + dq] =
                *(const uint4*)(k + (size_t)(b * TT + k0 + r) * EE + h * 64 + dq);
            *(uint4*)&Vs[r * FSTR + dq] =
                *(const uint4*)(v + (size_t)(b * TT + k0 + r) * EE + h * 64 + dq);
        }
        __syncthreads();

        float accS[8][4] = {};
        #pragma unroll
        for (int kb = 0; kb < 64; kb += 16) {
            uint32_t af[4];
            ldsm4(af, qsb + ((wq + lrow) * FSTR + kb + lk) * 2);
            #pragma unroll
            for (int nj = 0; nj < 4; nj++) {
                uint32_t r[4];
                ldsm4(r, ksb + ((nj * 16 + lrow) * FSTR + kb + lk) * 2);
                uint32_t bf0[2] = { r[0], r[2] };
                uint32_t bf1[2] = { r[1], r[3] };
                mma_f16(accS[2*nj],   af, bf0);
                mma_f16(accS[2*nj+1], af, bf1);
            }
        }

        bool diag = (kt == qt);
        #pragma unroll
        for (int ni = 0; ni < 8; ni++) {
            int c = ni * 8 + t * 2;
            accS[ni][0] *= scale; accS[ni][1] *= scale;
            accS[ni][2] *= scale; accS[ni][3] *= scale;
            if (diag) {
                if (c     > r0)     accS[ni][0] = -1e30f;
                if (c + 1 > r0)     accS[ni][1] = -1e30f;
                if (c     > r0 + 8) accS[ni][2] = -1e30f;
                if (c + 1 > r0 + 8) accS[ni][3] = -1e30f;
            }
        }

        float m0 = -1e30f, m1 = -1e30f;
        #pragma unroll
        for (int ni = 0; ni < 8; ni++) {
            m0 = fmaxf(m0, fmaxf(accS[ni][0], accS[ni][1]));
            m1 = fmaxf(m1, fmaxf(accS[ni][2], accS[ni][3]));
        }
        m0 = fmaxf(m0, __shfl_xor_sync(0xffffffffu, m0, 1));
        m0 = fmaxf(m0, __shfl_xor_sync(0xffffffffu, m0, 2));
        m1 = fmaxf(m1, __shfl_xor_sync(0xffffffffu, m1, 1));
        m1 = fmaxf(m1, __shfl_xor_sync(0xffffffffu, m1, 2));

        float mn0 = fmaxf(mr0, m0), mn1 = fmaxf(mr1, m1);
        float a0 = fexp(mr0 - mn0), a1 = fexp(mr1 - mn1);

        float s0 = 0.f, s1 = 0.f;
        #pragma unroll
        for (int ni = 0; ni < 8; ni++) {
            accS[ni][0] = fexp(accS[ni][0] - mn0);
            accS[ni][1] = fexp(accS[ni][1] - mn0);
            accS[ni][2] = fexp(accS[ni][2] - mn1);
            accS[ni][3] = fexp(accS[ni][3] - mn1);
            s0 += accS[ni][0] + accS[ni][1];
            s1 += accS[ni][2] + accS[ni][3];
        }
        s0 += __shfl_xor_sync(0xffffffffu, s0, 1);
        s0 += __shfl_xor_sync(0xffffffffu, s0, 2);
        s1 += __shfl_xor_sync(0xffffffffu, s1, 1);
        s1 += __shfl_xor_sync(0xffffffffu, s1, 2);

        lr0 = lr0 * a0 + s0;
        lr1 = lr1 * a1 + s1;
        mr0 = mn0; mr1 = mn1;

        #pragma unroll
        for (int ni = 0; ni < 8; ni++) {
            accO[ni][0] *= a0; accO[ni][1] *= a0;
            accO[ni][2] *= a1; accO[ni][3] *= a1;
        }

        #pragma unroll
        for (int ni = 0; ni < 8; ni++) {
            int c = ni * 8 + 2 * t;
            *(__half2*)&Ps[r0 * FSTR + c]       = __floats2half2_rn(accS[ni][0], accS[ni][1]);
            *(__half2*)&Ps[(r0 + 8) * FSTR + c] = __floats2half2_rn(accS[ni][2], accS[ni][3]);
        }
        __syncwarp();

        #pragma unroll
        for (int kb = 0; kb < 64; kb += 16) {
            uint32_t af[4];
            ldsm4(af, psb + ((wq + lrow) * FSTR + kb + lk) * 2);
            #pragma unroll
            for (int nj = 0; nj < 4; nj++) {
                uint32_t r[4];
                ldsm4t(r, vsb + ((kb + lrow) * FSTR + nj * 16 + lk) * 2);
                uint32_t bf0[2] = { r[0], r[1] };
                uint32_t bf1[2] = { r[2], r[3] };
                mma_f16(accO[2*nj],   af, bf0);
                mma_f16(accO[2*nj+1], af, bf1);
            }
        }
    }

    float i0 = 1.f / lr0, i1 = 1.f / lr1;
    #pragma unroll
    for (int ni = 0; ni < 8; ni++) {
        int d = ni * 8 + 2 * t;
        *(__half2*)(o + (size_t)(b * TT + q0 + r0) * EE + h * 64 + d) =
            __floats2half2_rn(accO[ni][0] * i0, accO[ni][1] * i0);
        *(__half2*)(o + (size_t)(b * TT + q0 + r0 + 8) * EE + h * 64 + d) =
            __floats2half2_rn(accO[ni][2] * i1, accO[ni][3] * i1);
    }
}

// ---------------- cross-entropy ----------------
__global__ void loss_row_kernel(const float* __restrict__ logits, const int* __restrict__ targets,
                                float* __restrict__ rowloss)
{
    int row = blockIdx.x;
    const float* lr = logits + (size_t)row * VV;
    __shared__ float red[256];
    int tid = threadIdx.x;

    float m = -1e30f;
    for (int i = tid; i < VV / 4; i += 256) {
        float4 v = ((const float4*)lr)[i];
        m = fmaxf(m, fmaxf(fmaxf(v.x, v.y), fmaxf(v.z, v.w)));
    }
    red[tid] = m; __syncthreads();
    for (int o = 128; o > 0; o >>= 1) { if (tid < o) red[tid] = fmaxf(red[tid], red[tid + o]); __syncthreads(); }
    m = red[0]; __syncthreads();

    float s = 0.f;
    for (int i = tid; i < VV / 4; i += 256) {
        float4 v = ((const float4*)lr)[i];
        s += fexp(v.x - m) + fexp(v.y - m) + fexp(v.z - m) + fexp(v.w - m);
    }
    red[tid] = s; __syncthreads();
    for (int o = 128; o > 0; o >>= 1) { if (tid < o) red[tid] += red[tid + o]; __syncthreads(); }

    if (tid == 0) {
        float lse = m + logf(red[0]);
        rowloss[row] = lse - lr[targets[row]];
    }
}

__global__ void loss_reduce_kernel(const float* __restrict__ rowloss, float* __restrict__ out)
{
    __shared__ float red[256];
    int tid = threadIdx.x;
    float s = 0.f;
    for (int i = tid; i < MROWS; i += 256) s += rowloss[i];
    red[tid] = s; __syncthreads();
    for (int o = 128; o > 0; o >>= 1) { if (tid < o) red[tid] += red[tid + o]; __syncthreads(); }
    if (tid == 0) out[0] = red[0] * (1.0f / MROWS);
}

// ---------------- host orchestration ----------------
#define SMEMG (NSTG * (ASZH + BSZH) * 2)   // 75776 bytes

extern "C" void kernel_launch(void* const* d_in, const int* in_sizes, int n_in,
                              void* d_out, int out_size)
{
    const int*   ctx  = (const int*)  d_in[0];
    const int*   tgt  = (const int*)  d_in[1];
    const float* tok  = (const float*)d_in[2];
    const float* pos  = (const float*)d_in[3];
    const float* Wq   = (const float*)d_in[4];
    const float* Wk   = (const float*)d_in[5];
    const float* Wv   = (const float*)d_in[6];
    const float* Wo   = (const float*)d_in[7];
    const float* bo   = (const float*)d_in[8];
    const float* ln1g = (const float*)d_in[9];
    const float* ln1b = (const float*)d_in[10];
    const float* ln2g = (const float*)d_in[11];
    const float* ln2b = (const float*)d_in[12];
    const float* W1   = (const float*)d_in[13];
    const float* b1   = (const float*)d_in[14];
    const float* W2   = (const float*)d_in[15];
    const float* b2   = (const float*)d_in[16];
    const float* lnfg = (const float*)d_in[17];
    const float* lnfb = (const float*)d_in[18];
    const float* Wlm  = (const float*)d_in[19];
    const float* blm  = (const float*)d_in[20];

    static float *px = nullptr, *prl;
    static __half *ph, *pq, *pk, *pv, *po, *pff;
    static __half *whq, *whk, *whv, *who, *wh1, *wh2, *whlm;
    if (!px) {
        cudaGetSymbolAddress((void**)&px,  g_x);
        cudaGetSymbolAddress((void**)&prl, g_rowloss);
        cudaGetSymbolAddress((void**)&ph,  g_h);
        cudaGetSymbolAddress((void**)&pq,  g_q);
        cudaGetSymbolAddress((void**)&pk,  g_k);
        cudaGetSymbolAddress((void**)&pv,  g_v);
        cudaGetSymbolAddress((void**)&po,  g_o);
        cudaGetSymbolAddress((void**)&pff, g_ff);
        cudaGetSymbolAddress((void**)&whq, g_whq);
        cudaGetSymbolAddress((void**)&whk, g_whk);
        cudaGetSymbolAddress((void**)&whv, g_whv);
        cudaGetSymbolAddress((void**)&who, g_who);
        cudaGetSymbolAddress((void**)&wh1, g_wh1);
        cudaGetSymbolAddress((void**)&wh2, g_wh2);
        cudaGetSymbolAddress((void**)&whlm, g_whlm);
        cudaFuncSetAttribute(hgemm_kernel, cudaFuncAttributeMaxDynamicSharedMemorySize, SMEMG);
    }
    float* out = (float*)d_out;

    conv_h<<<4096, 256>>>((const float4*)Wq,  (uint2*)whq,  LL*EE*EE/4);
    conv_h<<<4096, 256>>>((const float4*)Wk,  (uint2*)whk,  LL*EE*EE/4);
    conv_h<<<4096, 256>>>((const float4*)Wv,  (uint2*)whv,  LL*EE*EE/4);
    conv_h<<<4096, 256>>>((const float4*)Wo,  (uint2*)who,  LL*EE*EE/4);
    conv_h<<<8192, 256>>>((const float4*)W1,  (uint2*)wh1,  LL*EE*FF_/4);
    conv_h<<<8192, 256>>>((const float4*)W2,  (uint2*)wh2,  LL*FF_*EE/4);
    conv_h<<<8192, 256>>>((const float4*)Wlm, (uint2*)whlm, EE*VV/4);

    embed_kernel<<<MROWS, 256>>>(ctx, tok, pos, px);

    // grids: (M tiles, N tiles)  -- x = rows (fastest) for B-tile L2 reuse
    dim3 gQKV(16, 24);
    dim3 gEo (16, 8);
    dim3 gF1 (16, 32);
    dim3 gLM (16, 250);
    dim3 gFA (32, 16);     // (bh, q tiles reversed)

    for (int l = 0; l < LL; l++) {
        size_t oE = (size_t)l * EE * EE, oF = (size_t)l * EE * FF_;

        ln_kernel<<<MROWS, 256>>>(px, ln1g + l * EE, ln1b + l * EE, ph);

        hgemm_kernel<<<gQKV, 256, SMEMG>>>(ph, whq + oE, whk + oE, whv + oE, EE,
                                           nullptr, nullptr, pq, pk, pv, EE, 0, 1);

        flash_kernel<<<gFA, 128>>>(pq, pk, pv, po);

        hgemm_kernel<<<gEo, 256, SMEMG>>>(po, who + oE, who + oE, who + oE, EE,
                                          bo + l * EE, px, px, px, px, EE, 0, 0);

        ln_kernel<<<MROWS, 256>>>(px, ln2g + l * EE, ln2b + l * EE, ph);

        hgemm_kernel<<<gF1, 256, SMEMG>>>(ph, wh1 + oF, wh1 + oF, wh1 + oF, FF_,
                                          b1 + l * FF_, nullptr, pff, pff, pff, EE, 1, 1);

        hgemm_kernel<<<gEo, 256, SMEMG>>>(pff, wh2 + oF, wh2 + oF, wh2 + oF, EE,
                                          b2 + l * EE, px, px, px, px, FF_, 0, 0);
    }

    ln_kernel<<<MROWS, 256>>>(px, lnfg, lnfb, ph);
    hgemm_kernel<<<gLM, 256, SMEMG>>>(ph, whlm, whlm, whlm, VV,
                                      blm, nullptr, out, out, out, EE, 0, 0);

    if (out_size > MROWS * VV) {
        loss_row_kernel<<<MROWS, 256>>>(out, tgt, prl);
        loss_reduce_kernel<<<1, 256>>>(prl, out + (size_t)MROWS * VV);
    }
}

// round 9
// speedup vs baseline: 2.1170x; 1.0099x over previous
#include <cuda_runtime.h>
#include <cuda_fp16.h>
#include <math.h>
#include <stdint.h>

#define BB   2
#define TT   1024
#define EE   1024
#define HH   16
#define HD   64
#define LL   8
#define FF_  4096
#define VV   32000
#define MROWS (BB*TT)          // 2048

// ---------------- scratch ----------------
__device__ float  g_x  [MROWS*EE];
__device__ __half g_h  [MROWS*EE];
__device__ __half g_q  [MROWS*EE];
__device__ __half g_k  [MROWS*EE];
__device__ __half g_v  [MROWS*EE];
__device__ __half g_o  [MROWS*EE];
__device__ __half g_ff [MROWS*FF_];
__device__ float  g_rowloss[MROWS];
__device__ __half g_whq[LL*EE*EE];
__device__ __half g_whk[LL*EE*EE];
__device__ __half g_whv[LL*EE*EE];
__device__ __half g_who[LL*EE*EE];
__device__ __half g_wh1[LL*EE*FF_];
__device__ __half g_wh2[LL*FF_*EE];
__device__ __half g_whlm[(size_t)EE*VV];

// ---------------- helpers ----------------
__device__ __forceinline__ void mma_f16(float* d, const uint32_t* a, const uint32_t* b) {
    asm volatile(
        "mma.sync.aligned.m16n8k16.row.col.f32.f16.f16.f32 "
        "{%0,%1,%2,%3}, {%4,%5,%6,%7}, {%8,%9}, {%0,%1,%2,%3};"
        : "+f"(d[0]), "+f"(d[1]), "+f"(d[2]), "+f"(d[3])
        : "r"(a[0]), "r"(a[1]), "r"(a[2]), "r"(a[3]), "r"(b[0]), "r"(b[1]));
}
__device__ __forceinline__ void ldsm4(uint32_t* r, uint32_t addr) {
    asm volatile("ldmatrix.sync.aligned.m8n8.x4.shared.b16 {%0,%1,%2,%3}, [%4];"
        : "=r"(r[0]), "=r"(r[1]), "=r"(r[2]), "=r"(r[3]) : "r"(addr));
}
__device__ __forceinline__ void ldsm4t(uint32_t* r, uint32_t addr) {
    asm volatile("ldmatrix.sync.aligned.m8n8.x4.trans.shared.b16 {%0,%1,%2,%3}, [%4];"
        : "=r"(r[0]), "=r"(r[1]), "=r"(r[2]), "=r"(r[3]) : "r"(addr));
}
__device__ __forceinline__ uint32_t smem_u32(const void* p) {
    return (uint32_t)__cvta_generic_to_shared(p);
}
__device__ __forceinline__ void cp16h(__half* s, const __half* g) {
    uint32_t sa = smem_u32(s);
    asm volatile("cp.async.ca.shared.global [%0], [%1], 16;" :: "r"(sa), "l"(g));
}
#define CP_COMMIT() asm volatile("cp.async.commit_group;")

// fast exp on FMA/ALU pipes
__device__ __forceinline__ float fexp(float x) {
    float y = fmaxf(x * 1.44269504f, -126.0f);
    float t = y + 12582912.0f;
    int   e = __float_as_int(t);
    float r = t - 12582912.0f;
    float f = y - r;
    float p = 1.0f + f * (0.693147180f + f * (0.240226507f + f * (0.055504109f +
                     f * (0.009618130f + f * 0.001333356f))));
    return __int_as_float((e - 0x4B400000 + 127) << 23) * p;
}

// ---------------- streaming fp32 -> fp16 convert (32B load / 16B store per thread) ---
__global__ void conv_h2(const float4* __restrict__ in, uint4* __restrict__ out, int n8)
{
    int i = blockIdx.x * blockDim.x + threadIdx.x;
    int stride = gridDim.x * blockDim.x;
    for (; i < n8; i += stride) {
        float4 a = in[2 * i], b = in[2 * i + 1];
        __half2 h0 = __floats2half2_rn(a.x, a.y);
        __half2 h1 = __floats2half2_rn(a.z, a.w);
        __half2 h2 = __floats2half2_rn(b.x, b.y);
        __half2 h3 = __floats2half2_rn(b.z, b.w);
        out[i] = make_uint4(*(uint32_t*)&h0, *(uint32_t*)&h1,
                            *(uint32_t*)&h2, *(uint32_t*)&h3);
    }
}

// ---------------- embedding ----------------
__global__ void embed_kernel(const int* __restrict__ ctx, const float* __restrict__ tok,
                             const float* __restrict__ pos, float* __restrict__ x)
{
    int row = blockIdx.x;
    int t   = row % TT;
    int token = ctx[row];
    int tid = threadIdx.x;
    float4 te = ((const float4*)(tok + (size_t)token * EE))[tid];
    float4 pe = ((const float4*)(pos + (size_t)t * EE))[tid];
    ((float4*)(x + (size_t)row * EE))[tid] =
        make_float4(te.x + pe.x, te.y + pe.y, te.z + pe.z, te.w + pe.w);
}

// ---------------- layernorm: WARP per row, no block syncs ----------------
__global__ void ln_kernel(const float* __restrict__ x, const float* __restrict__ g,
                          const float* __restrict__ b, __half* __restrict__ y)
{
    int warp = threadIdx.x >> 5, lane = threadIdx.x & 31;
    int row = blockIdx.x * 8 + warp;
    const float4* xr = (const float4*)(x + (size_t)row * EE);
    float4 xv[8];
    float s = 0.f, q = 0.f;
    #pragma unroll
    for (int i = 0; i < 8; i++) {
        xv[i] = xr[lane + 32 * i];
        s += xv[i].x + xv[i].y + xv[i].z + xv[i].w;
        q += xv[i].x * xv[i].x + xv[i].y * xv[i].y + xv[i].z * xv[i].z + xv[i].w * xv[i].w;
    }
    #pragma unroll
    for (int o = 16; o; o >>= 1) {
        s += __shfl_xor_sync(0xffffffffu, s, o);
        q += __shfl_xor_sync(0xffffffffu, q, o);
    }
    float mu  = s * (1.0f / EE);
    float var = fmaxf(q * (1.0f / EE) - mu * mu, 0.f);
    float rs  = rsqrtf(var + 1e-5f);
    __half* yr = y + (size_t)row * EE;
    #pragma unroll
    for (int i = 0; i < 8; i++) {
        float4 gv = ((const float4*)g)[lane + 32 * i];
        float4 bv = ((const float4*)b)[lane + 32 * i];
        __half2 h0 = __floats2half2_rn((xv[i].x - mu) * rs * gv.x + bv.x,
                                       (xv[i].y - mu) * rs * gv.y + bv.y);
        __half2 h1 = __floats2half2_rn((xv[i].z - mu) * rs * gv.z + bv.z,
                                       (xv[i].w - mu) * rs * gv.w + bv.w);
        *(uint2*)(yr + (lane + 32 * i) * 4) = make_uint2(*(uint32_t*)&h0, *(uint32_t*)&h1);
    }
}

// ---------------- fp16 GEMM (unchanged from round 8) ----------------
#define HSTR 40
#define ASZH (128*HSTR)
#define BSTRH 136
#define BSZH (32*BSTRH)
#define NSTG 4

__global__ __launch_bounds__(256, 2) void hgemm_kernel(
    const __half* __restrict__ A,
    const __half* __restrict__ w0, const __half* __restrict__ w1, const __half* __restrict__ w2,
    int wN,
    const float* __restrict__ bias, const float* __restrict__ res,
    void* c0, void* c1, void* c2,
    int K, int relu, int outHalf)
{
    extern __shared__ __half sm[];
    __half* As = sm;
    __half* Bs = sm + NSTG * ASZH;

    int tid = threadIdx.x;
    int warp = tid >> 5, lane = tid & 31;
    int g = lane >> 2, t = lane & 3;
    int lrow = lane & 15, lk = (lane >> 4) * 8;
    int wm = (warp & 3) * 32;
    int wn = (warp >> 2) * 64;
    int row0 = blockIdx.x * 128;
    int col0 = blockIdx.y * 128;

    int chunk = col0 / wN;
    int lcol0 = col0 - chunk * wN;
    const __half* W = (chunk == 0) ? w0 : (chunk == 1 ? w1 : w2);
    void* C = (chunk == 0) ? c0 : (chunk == 1 ? c1 : c2);
    const __half* Ab = A + (size_t)row0 * K;
    const __half* Wb = W + lcol0;

    float acc[2][8][4] = {};

    auto issue = [&](int st, int k0) {
        __half* as = As + st * ASZH;
        __half* bs = Bs + st * BSZH;
        #pragma unroll
        for (int i = 0; i < 2; i++) {
            int idx = tid + i * 256;
            int m = idx >> 2, kq = (idx & 3) * 8;
            cp16h(&as[m * HSTR + kq], Ab + (size_t)m * K + k0 + kq);
            int kr = idx >> 4, nq = (idx & 15) * 8;
            cp16h(&bs[kr * BSTRH + nq], Wb + (size_t)(k0 + kr) * wN + nq);
        }
    };
    auto compute = [&](int st) {
        uint32_t asb = smem_u32(As + st * ASZH);
        uint32_t bsb = smem_u32(Bs + st * BSZH);
        #pragma unroll
        for (int kk = 0; kk < 2; kk++) {
            int kb = kk * 16;
            uint32_t af[2][4], bf[8][2];
            #pragma unroll
            for (int mi = 0; mi < 2; mi++)
                ldsm4(af[mi], asb + ((wm + mi * 16 + lrow) * HSTR + kb + lk) * 2);
            #pragma unroll
            for (int nj = 0; nj < 4; nj++) {
                uint32_t r[4];
                ldsm4t(r, bsb + ((kb + lrow) * BSTRH + wn + nj * 16 + lk) * 2);
                bf[2*nj][0]   = r[0]; bf[2*nj][1]   = r[1];
                bf[2*nj+1][0] = r[2]; bf[2*nj+1][1] = r[3];
            }
            #pragma unroll
            for (int mi = 0; mi < 2; mi++)
                #pragma unroll
                for (int ni = 0; ni < 8; ni++)
                    mma_f16(acc[mi][ni], af[mi], bf[ni]);
        }
    };

    int nks = K >> 5;
    issue(0, 0);  CP_COMMIT();
    issue(1, 32); CP_COMMIT();
    issue(2, 64); CP_COMMIT();
    for (int ks = 0; ks < nks; ks++) {
        int s = ks & (NSTG - 1);
        asm volatile("cp.async.wait_group 2;");
        __syncthreads();
        int kpf = ks + 3;
        if (kpf < nks) issue(kpf & (NSTG - 1), kpf * 32);
        CP_COMMIT();
        compute(s);
    }

    #pragma unroll
    for (int mi = 0; mi < 2; mi++) {
        int r = row0 + wm + mi * 16 + g;
        #pragma unroll
        for (int ni = 0; ni < 8; ni++) {
            int c = lcol0 + wn + ni * 8 + t * 2;
            float v0 = acc[mi][ni][0], v1 = acc[mi][ni][1];
            float v2 = acc[mi][ni][2], v3 = acc[mi][ni][3];
            if (bias) { float b0 = bias[c], b1 = bias[c + 1]; v0 += b0; v1 += b1; v2 += b0; v3 += b1; }
            if (res) {
                v0 += res[(size_t)r * wN + c];       v1 += res[(size_t)r * wN + c + 1];
                v2 += res[(size_t)(r + 8) * wN + c]; v3 += res[(size_t)(r + 8) * wN + c + 1];
            }
            if (relu) { v0 = fmaxf(v0, 0.f); v1 = fmaxf(v1, 0.f); v2 = fmaxf(v2, 0.f); v3 = fmaxf(v3, 0.f); }
            if (outHalf) {
                __half* Ch = (__half*)C;
                *(__half2*)&Ch[(size_t)r * wN + c]       = __floats2half2_rn(v0, v1);
                *(__half2*)&Ch[(size_t)(r + 8) * wN + c] = __floats2half2_rn(v2, v3);
            } else {
                float* Cf = (float*)C;
                *(float2*)&Cf[(size_t)r * wN + c]       = make_float2(v0, v1);
                *(float2*)&Cf[(size_t)(r + 8) * wN + c] = make_float2(v2, v3);
            }
        }
    }
}

// ---------------- fused flash attention: cp.async double-buffered K/V ---------------
#define FSTR 72
#define FTSZ (64*FSTR)
__global__ __launch_bounds__(128, 3) void flash_kernel(
    const __half* __restrict__ q, const __half* __restrict__ k,
    const __half* __restrict__ v, __half* __restrict__ o)
{
    extern __shared__ __half fsm[];
    __half* Qs = fsm;                  // [64][FSTR]
    __half* Ps = fsm + FTSZ;           // [64][FSTR]
    __half* Ks = fsm + 2 * FTSZ;       // 2 buffers
    __half* Vs = fsm + 4 * FTSZ;       // 2 buffers

    int bh = blockIdx.x;
    int qt = (int)gridDim.y - 1 - (int)blockIdx.y;   // heavy tiles first
    int b = bh >> 4, h = bh & 15;
    int q0 = qt * 64;

    int tid = threadIdx.x;
    int warp = tid >> 5, lane = tid & 31;
    int g = lane >> 2, t = lane & 3;
    int lrow = lane & 15, lk = (lane >> 4) * 8;
    int wq = warp * 16;
    int r0 = wq + g;

    uint32_t qsb = smem_u32(Qs), psb = smem_u32(Ps);

    auto issueKV = [&](int buf, int k0) {
        __half* Kd = Ks + buf * FTSZ;
        __half* Vd = Vs + buf * FTSZ;
        #pragma unroll
        for (int i = 0; i < 4; i++) {
            int idx = tid + i * 128;
            int r = idx >> 3, dq = (idx & 7) * 8;
            const __half* kp = k + (size_t)(b * TT + k0 + r) * EE + h * 64 + dq;
            const __half* vp = v + (size_t)(b * TT + k0 + r) * EE + h * 64 + dq;
            cp16h(&Kd[r * FSTR + dq], kp);
            cp16h(&Vd[r * FSTR + dq], vp);
        }
    };

    // Q tile + first K/V tile
    #pragma unroll
    for (int i = 0; i < 4; i++) {
        int idx = tid + i * 128;
        int r = idx >> 3, dq = (idx & 7) * 8;
        *(uint4*)&Qs[r * FSTR + dq] =
            *(const uint4*)(q + (size_t)(b * TT + q0 + r) * EE + h * 64 + dq);
    }
    issueKV(0, q0 - q0);           // kt=0 -> k0=0
    CP_COMMIT();

    float accO[8][4] = {};
    float mr0 = -1e30f, mr1 = -1e30f, lr0 = 0.f, lr1 = 0.f;
    const float scale = 0.03125f;

    for (int kt = 0; kt <= qt; kt++) {
        int buf = kt & 1;
        __syncthreads();   // all warps done with buf^1 (tile kt-1); Q visible on kt=0
        if (kt < qt) {
            issueKV(buf ^ 1, (kt + 1) * 64);
            CP_COMMIT();
            asm volatile("cp.async.wait_group 1;");
        } else {
            asm volatile("cp.async.wait_group 0;");
        }
        __syncthreads();

        uint32_t ksb = smem_u32(Ks + buf * FTSZ);
        uint32_t vsb = smem_u32(Vs + buf * FTSZ);

        float accS[8][4] = {};
        #pragma unroll
        for (int kb = 0; kb < 64; kb += 16) {
            uint32_t af[4];
            ldsm4(af, qsb + ((wq + lrow) * FSTR + kb + lk) * 2);
            #pragma unroll
            for (int nj = 0; nj < 4; nj++) {
                uint32_t r[4];
                ldsm4(r, ksb + ((nj * 16 + lrow) * FSTR + kb + lk) * 2);
                uint32_t bf0[2] = { r[0], r[2] };
                uint32_t bf1[2] = { r[1], r[3] };
                mma_f16(accS[2*nj],   af, bf0);
                mma_f16(accS[2*nj+1], af, bf1);
            }
        }

        bool diag = (kt == qt);
        #pragma unroll
        for (int ni = 0; ni < 8; ni++) {
            int c = ni * 8 + t * 2;
            accS[ni][0] *= scale; accS[ni][1] *= scale;
            accS[ni][2] *= scale; accS[ni][3] *= scale;
            if (diag) {
                if (c     > r0)     accS[ni][0] = -1e30f;
                if (c + 1 > r0)     accS[ni][1] = -1e30f;
                if (c     > r0 + 8) accS[ni][2] = -1e30f;
                if (c + 1 > r0 + 8) accS[ni][3] = -1e30f;
            }
        }

        float m0 = -1e30f, m1 = -1e30f;
        #pragma unroll
        for (int ni = 0; ni < 8; ni++) {
            m0 = fmaxf(m0, fmaxf(accS[ni][0], accS[ni][1]));
            m1 = fmaxf(m1, fmaxf(accS[ni][2], accS[ni][3]));
        }
        m0 = fmaxf(m0, __shfl_xor_sync(0xffffffffu, m0, 1));
        m0 = fmaxf(m0, __shfl_xor_sync(0xffffffffu, m0, 2));
        m1 = fmaxf(m1, __shfl_xor_sync(0xffffffffu, m1, 1));
        m1 = fmaxf(m1, __shfl_xor_sync(0xffffffffu, m1, 2));

        float mn0 = fmaxf(mr0, m0), mn1 = fmaxf(mr1, m1);
        float a0 = fexp(mr0 - mn0), a1 = fexp(mr1 - mn1);

        float s0 = 0.f, s1 = 0.f;
        #pragma unroll
        for (int ni = 0; ni < 8; ni++) {
            accS[ni][0] = fexp(accS[ni][0] - mn0);
            accS[ni][1] = fexp(accS[ni][1] - mn0);
            accS[ni][2] = fexp(accS[ni][2] - mn1);
            accS[ni][3] = fexp(accS[ni][3] - mn1);
            s0 += accS[ni][0] + accS[ni][1];
            s1 += accS[ni][2] + accS[ni][3];
        }
        s0 += __shfl_xor_sync(0xffffffffu, s0, 1);
        s0 += __shfl_xor_sync(0xffffffffu, s0, 2);
        s1 += __shfl_xor_sync(0xffffffffu, s1, 1);
        s1 += __shfl_xor_sync(0xffffffffu, s1, 2);

        lr0 = lr0 * a0 + s0;
        lr1 = lr1 * a1 + s1;
        mr0 = mn0; mr1 = mn1;

        #pragma unroll
        for (int ni = 0; ni < 8; ni++) {
            accO[ni][0] *= a0; accO[ni][1] *= a0;
            accO[ni][2] *= a1; accO[ni][3] *= a1;
        }

        #pragma unroll
        for (int ni = 0; ni < 8; ni++) {
            int c = ni * 8 + 2 * t;
            *(__half2*)&Ps[r0 * FSTR + c]       = __floats2half2_rn(accS[ni][0], accS[ni][1]);
            *(__half2*)&Ps[(r0 + 8) * FSTR + c] = __floats2half2_rn(accS[ni][2], accS[ni][3]);
        }
        __syncwarp();

        #pragma unroll
        for (int kb = 0; kb < 64; kb += 16) {
            uint32_t af[4];
            ldsm4(af, psb + ((wq + lrow) * FSTR + kb + lk) * 2);
            #pragma unroll
            for (int nj = 0; nj < 4; nj++) {
                uint32_t r[4];
                ldsm4t(r, vsb + ((kb + lrow) * FSTR + nj * 16 + lk) * 2);
                uint32_t bf0[2] = { r[0], r[1] };
                uint32_t bf1[2] = { r[2], r[3] };
                mma_f16(accO[2*nj],   af, bf0);
                mma_f16(accO[2*nj+1], af, bf1);
            }
        }
    }

    float i0 = 1.f / lr0, i1 = 1.f / lr1;
    #pragma unroll
    for (int ni = 0; ni < 8; ni++) {
        int d = ni * 8 + 2 * t;
        *(__half2*)(o + (size_t)(b * TT + q0 + r0) * EE + h * 64 + d) =
            __floats2half2_rn(accO[ni][0] * i0, accO[ni][1] * i0);
        *(__half2*)(o + (size_t)(b * TT + q0 + r0 + 8) * EE + h * 64 + d) =
            __floats2half2_rn(accO[ni][2] * i1, accO[ni][3] * i1);
    }
}

// ---------------- cross-entropy ----------------
__global__ void loss_row_kernel(const float* __restrict__ logits, const int* __restrict__ targets,
                                float* __restrict__ rowloss)
{
    int row = blockIdx.x;
    const float* lr = logits + (size_t)row * VV;
    __shared__ float red[256];
    int tid = threadIdx.x;

    float m = -1e30f;
    for (int i = tid; i < VV / 4; i += 256) {
        float4 v = ((const float4*)lr)[i];
        m = fmaxf(m, fmaxf(fmaxf(v.x, v.y), fmaxf(v.z, v.w)));
    }
    red[tid] = m; __syncthreads();
    for (int o = 128; o > 0; o >>= 1) { if (tid < o) red[tid] = fmaxf(red[tid], red[tid + o]); __syncthreads(); }
    m = red[0]; __syncthreads();

    float s = 0.f;
    for (int i = tid; i < VV / 4; i += 256) {
        float4 v = ((const float4*)lr)[i];
        s += fexp(v.x - m) + fexp(v.y - m) + fexp(v.z - m) + fexp(v.w - m);
    }
    red[tid] = s; __syncthreads();
    for (int o = 128; o > 0; o >>= 1) { if (tid < o) red[tid] += red[tid + o]; __syncthreads(); }

    if (tid == 0) {
        float lse = m + logf(red[0]);
        rowloss[row] = lse - lr[targets[row]];
    }
}

__global__ void loss_reduce_kernel(const float* __restrict__ rowloss, float* __restrict__ out)
{
    __shared__ float red[256];
    int tid = threadIdx.x;
    float s = 0.f;
    for (int i = tid; i < MROWS; i += 256) s += rowloss[i];
    red[tid] = s; __syncthreads();
    for (int o = 128; o > 0; o >>= 1) { if (tid < o) red[tid] += red[tid + o]; __syncthreads(); }
    if (tid == 0) out[0] = red[0] * (1.0f / MROWS);
}

// ---------------- host orchestration ----------------
#define SMEMG (NSTG * (ASZH + BSZH) * 2)   // 75776
#define SMEMF (6 * FTSZ * 2)               // 55296

extern "C" void kernel_launch(void* const* d_in, const int* in_sizes, int n_in,
                              void* d_out, int out_size)
{
    const int*   ctx  = (const int*)  d_in[0];
    const int*   tgt  = (const int*)  d_in[1];
    const float* tok  = (const float*)d_in[2];
    const float* pos  = (const float*)d_in[3];
    const float* Wq   = (const float*)d_in[4];
    const float* Wk   = (const float*)d_in[5];
    const float* Wv   = (const float*)d_in[6];
    const float* Wo   = (const float*)d_in[7];
    const float* bo   = (const float*)d_in[8];
    const float* ln1g = (const float*)d_in[9];
    const float* ln1b = (const float*)d_in[10];
    const float* ln2g = (const float*)d_in[11];
    const float* ln2b = (const float*)d_in[12];
    const float* W1   = (const float*)d_in[13];
    const float* b1   = (const float*)d_in[14];
    const float* W2   = (const float*)d_in[15];
    const float* b2   = (const float*)d_in[16];
    const float* lnfg = (const float*)d_in[17];
    const float* lnfb = (const float*)d_in[18];
    const float* Wlm  = (const float*)d_in[19];
    const float* blm  = (const float*)d_in[20];

    static float *px = nullptr, *prl;
    static __half *ph, *pq, *pk, *pv, *po, *pff;
    static __half *whq, *whk, *whv, *who, *wh1, *wh2, *whlm;
    if (!px) {
        cudaGetSymbolAddress((void**)&px,  g_x);
        cudaGetSymbolAddress((void**)&prl, g_rowloss);
        cudaGetSymbolAddress((void**)&ph,  g_h);
        cudaGetSymbolAddress((void**)&pq,  g_q);
        cudaGetSymbolAddress((void**)&pk,  g_k);
        cudaGetSymbolAddress((void**)&pv,  g_v);
        cudaGetSymbolAddress((void**)&po,  g_o);
        cudaGetSymbolAddress((void**)&pff, g_ff);
        cudaGetSymbolAddress((void**)&whq, g_whq);
        cudaGetSymbolAddress((void**)&whk, g_whk);
        cudaGetSymbolAddress((void**)&whv, g_whv);
        cudaGetSymbolAddress((void**)&who, g_who);
        cudaGetSymbolAddress((void**)&wh1, g_wh1);
        cudaGetSymbolAddress((void**)&wh2, g_wh2);
        cudaGetSymbolAddress((void**)&whlm, g_whlm);
        cudaFuncSetAttribute(hgemm_kernel, cudaFuncAttributeMaxDynamicSharedMemorySize, SMEMG);
        cudaFuncSetAttribute(flash_kernel, cudaFuncAttributeMaxDynamicSharedMemorySize, SMEMF);
    }
    float* out = (float*)d_out;

    conv_h2<<<4096, 256>>>((const float4*)Wq,  (uint4*)whq,  LL*EE*EE/8);
    conv_h2<<<4096, 256>>>((const float4*)Wk,  (uint4*)whk,  LL*EE*EE/8);
    conv_h2<<<4096, 256>>>((const float4*)Wv,  (uint4*)whv,  LL*EE*EE/8);
    conv_h2<<<4096, 256>>>((const float4*)Wo,  (uint4*)who,  LL*EE*EE/8);
    conv_h2<<<8192, 256>>>((const float4*)W1,  (uint4*)wh1,  LL*EE*FF_/8);
    conv_h2<<<8192, 256>>>((const float4*)W2,  (uint4*)wh2,  LL*FF_*EE/8);
    conv_h2<<<8192, 256>>>((const float4*)Wlm, (uint4*)whlm, EE*VV/8);

    embed_kernel<<<MROWS, 256>>>(ctx, tok, pos, px);

    dim3 gQKV(16, 24);
    dim3 gEo (16, 8);
    dim3 gF1 (16, 32);
    dim3 gLM (16, 250);
    dim3 gFA (32, 16);
    int gLN = MROWS / 8;   // warp per row

    for (int l = 0; l < LL; l++) {
        size_t oE = (size_t)l * EE * EE, oF = (size_t)l * EE * FF_;

        ln_kernel<<<gLN, 256>>>(px, ln1g + l * EE, ln1b + l * EE, ph);

        hgemm_kernel<<<gQKV, 256, SMEMG>>>(ph, whq + oE, whk + oE, whv + oE, EE,
                                           nullptr, nullptr, pq, pk, pv, EE, 0, 1);

        flash_kernel<<<gFA, 128, SMEMF>>>(pq, pk, pv, po);

        hgemm_kernel<<<gEo, 256, SMEMG>>>(po, who + oE, who + oE, who + oE, EE,
                                          bo + l * EE, px, px, px, px, EE, 0, 0);

        ln_kernel<<<gLN, 256>>>(px, ln2g + l * EE, ln2b + l * EE, ph);

        hgemm_kernel<<<gF1, 256, SMEMG>>>(ph, wh1 + oF, wh1 + oF, wh1 + oF, FF_,
                                          b1 + l * FF_, nullptr, pff, pff, pff, EE, 1, 1);

        hgemm_kernel<<<gEo, 256, SMEMG>>>(pff, wh2 + oF, wh2 + oF, wh2 + oF, EE,
                                          b2 + l * EE, px, px, px, px, FF_, 0, 0);
    }

    ln_kernel<<<gLN, 256>>>(px, lnfg, lnfb, ph);
    hgemm_kernel<<<gLM, 256, SMEMG>>>(ph, whlm, whlm, whlm, VV,
                                      blm, nullptr, out, out, out, EE, 0, 0);

    if (out_size > MROWS * VV) {
        loss_row_kernel<<<MROWS, 256>>>(out, tgt, prl);
        loss_reduce_kernel<<<1, 256>>>(prl, out + (size_t)MROWS * VV);
    }
}